// round 12
// baseline (speedup 1.0000x reference)
#include <cuda_runtime.h>
#include <cuda_bf16.h>
#include <math.h>
#include <stdint.h>

#define N_NODES 100000
#define N_EDGES 500000
#define N2 (2 * N_NODES)      // 200000
#define E2 (2 * N_EDGES)      // 1000000
#define NB1 782               // gemm1 blocks per net (ceil(100000/128))

// ---------------- scratch (static device globals; no allocation) ----------------
__device__ float g_h[(size_t)N2 * 128];        // layer1 conv output, both nets
__device__ float g_h3[(size_t)N2 * 64];        // layer2 conv output, both nets
__device__ float g_dis[N2];
__device__ float g_invdeg[N2];
__device__ int g_cnt[N2];
__device__ int g_rowstart[N2 + 1];
__device__ int g_cursor[N2];
__device__ int g_blocksums[1024];
__device__ int g_csr_src[E2];                  // global rows (net*N + s)
__device__ int g_csr_eidx[E2];                 // original edge position (net*E + e)
__device__ float g_csr_norm[E2];
__device__ __nv_bfloat16 g_w1h[128 * 128], g_w1l[128 * 128];
__device__ __nv_bfloat16 g_w2h[128 * 128], g_w2l[128 * 128];
__device__ __nv_bfloat16 g_w3h[64 * 128],  g_w3l[64 * 128];

// ---------------- pre-created side stream + events (static init; NOT during capture) ----
struct SideStream {
    cudaStream_t s;
    cudaEvent_t ev_fork, ev_join;
    SideStream() {
        cudaStreamCreateWithFlags(&s, cudaStreamNonBlocking);
        cudaEventCreateWithFlags(&ev_fork, cudaEventDisableTiming);
        cudaEventCreateWithFlags(&ev_join, cudaEventDisableTiming);
    }
};
static SideStream g_side;

__device__ __forceinline__ uint32_t smem_u32(const void* p) {
    uint32_t a;
    asm("{ .reg .u64 t; cvta.to.shared.u64 t, %1; cvt.u32.u64 %0, t; }" : "=r"(a) : "l"(p));
    return a;
}
__device__ __forceinline__ void split_bf16(float v, __nv_bfloat16& hi, __nv_bfloat16& lo) {
    hi = __float2bfloat16_rn(v);
    lo = __float2bfloat16_rn(v - __bfloat162float(hi));
}

// ---------------- degree + CSR build (both nets concatenated) ----------------
__global__ void deg_count_both(const int* __restrict__ s_ei, const int* __restrict__ t_ei) {
    int g = blockIdx.x * blockDim.x + threadIdx.x;
    if (g >= E2) return;
    int net = (g >= N_EDGES);
    int e = g - net * N_EDGES;
    const int* ei = net ? t_ei : s_ei;
    int d = ei[N_EDGES + e];
    atomicAdd(&g_cnt[net * N_NODES + d], 1);
}

__global__ void scan1_kernel() {
    __shared__ int s[2][256];
    int tid = threadIdx.x;
    int i = blockIdx.x * 256 + tid;
    int v = (i < N2) ? g_cnt[i] : 0;
    if (i < N2) {
        float d = (float)v + 1.0f;
        g_dis[i] = rsqrtf(d);
        g_invdeg[i] = 1.0f / d;
    }
    int buf = 0;
    s[0][tid] = v;
    __syncthreads();
#pragma unroll
    for (int off = 1; off < 256; off <<= 1) {
        int nb = buf ^ 1;
        s[nb][tid] = s[buf][tid] + (tid >= off ? s[buf][tid - off] : 0);
        buf = nb;
        __syncthreads();
    }
    if (i < N2) g_rowstart[i] = s[buf][tid] - v;
    if (tid == 255) g_blocksums[blockIdx.x] = s[buf][255];
}
__global__ void scan2_kernel(int nblocks) {
    __shared__ int s[2][1024];
    int tid = threadIdx.x;
    int v = (tid < nblocks) ? g_blocksums[tid] : 0;
    int buf = 0;
    s[0][tid] = v;
    __syncthreads();
#pragma unroll
    for (int off = 1; off < 1024; off <<= 1) {
        int nb = buf ^ 1;
        s[nb][tid] = s[buf][tid] + (tid >= off ? s[buf][tid - off] : 0);
        buf = nb;
        __syncthreads();
    }
    g_blocksums[tid] = s[buf][tid] - v;
}
__global__ void scan3_kernel() {
    int i = blockIdx.x * blockDim.x + threadIdx.x;
    if (i < N2) {
        int rs = g_rowstart[i] + g_blocksums[i >> 8];
        g_rowstart[i] = rs;
        g_cursor[i] = rs;
    }
    if (i == 0) g_rowstart[N2] = E2;
}
__global__ void csr_fill_both(const int* __restrict__ s_ei, const int* __restrict__ t_ei) {
    int g = blockIdx.x * blockDim.x + threadIdx.x;
    if (g >= E2) return;
    int net = (g >= N_EDGES);
    int e = g - net * N_EDGES;
    const int* ei = net ? t_ei : s_ei;
    int s = net * N_NODES + ei[e];
    int d = net * N_NODES + ei[N_EDGES + e];
    int pos = atomicAdd(&g_cursor[d], 1);
    g_csr_src[pos] = s;
    g_csr_eidx[pos] = g;
    g_csr_norm[pos] = g_dis[s] * g_dis[d];
}

// ---------------- weight prep ----------------
__global__ void prep_weights_kernel(const float* __restrict__ W1, const float* __restrict__ W2,
                                    const float* __restrict__ W3) {
    int tid = blockIdx.x * blockDim.x + threadIdx.x;
    if (tid < 128 * 128) {
        int n = tid >> 7, k = tid & 127;
        __nv_bfloat16 hi, lo;
        split_bf16(W1[k * 128 + n], hi, lo);
        g_w1h[n * 128 + k] = hi; g_w1l[n * 128 + k] = lo;
        split_bf16(W2[k * 128 + n], hi, lo);
        g_w2h[n * 128 + k] = hi; g_w2l[n * 128 + k] = lo;
        if (n < 64) {
            split_bf16(W3[k * 64 + n], hi, lo);
            g_w3h[n * 128 + k] = hi; g_w3l[n * 128 + k] = lo;
        }
    }
}

// ---------------- gemm1: bf16-split HMMA, both nets, chunked K ----------------
#define SKP 40

__global__ void __launch_bounds__(256) gemm1_both(
        const float* __restrict__ xs, const float* __restrict__ xt) {
    constexpr int NT = 8;
    __shared__ __nv_bfloat16 sAh[128][SKP];
    __shared__ __nv_bfloat16 sAl[128][SKP];
    __shared__ __nv_bfloat16 sBh[128][SKP];
    __shared__ __nv_bfloat16 sBl[128][SKP];

    const int tid = threadIdx.x;
    const int wid = tid >> 5, lane = tid & 31;
    const int warp_m = (wid & 3) * 32;
    const int warp_n = (wid >> 2) * 64;
    const int net = (blockIdx.x >= NB1);
    const int m0 = (blockIdx.x - net * NB1) * 128;
    const float* Af = net ? xt : xs;
    const __nv_bfloat16* Bh_g = net ? g_w2h : g_w1h;
    const __nv_bfloat16* Bl_g = net ? g_w2l : g_w1l;
    float* Ch = g_h + (size_t)net * N_NODES * 128;

    float acc[2][NT][4];
#pragma unroll
    for (int mt = 0; mt < 2; mt++)
#pragma unroll
        for (int nt = 0; nt < NT; nt++)
#pragma unroll
            for (int r = 0; r < 4; r++) acc[mt][nt][r] = 0.0f;

    const uint32_t sAh_b = smem_u32(&sAh[0][0]);
    const uint32_t sAl_b = smem_u32(&sAl[0][0]);
    const uint32_t sBh_b = smem_u32(&sBh[0][0]);
    const uint32_t sBl_b = smem_u32(&sBl[0][0]);
    const int a_row = warp_m + (lane & 15);
    const int a_khalf = (lane >> 4) << 3;
    const int b_row = warp_n + (lane & 7);
    const int b_khalf = lane & 8;

    for (int k0 = 0; k0 < 128; k0 += 32) {
#pragma unroll
        for (int it = 0; it < 4; it++) {
            int i = tid + it * 256;
            int r = i >> 3, c = (i & 7) * 4;
            float4 v = make_float4(0.f, 0.f, 0.f, 0.f);
            if (m0 + r < N_NODES) v = *(const float4*)&Af[(size_t)(m0 + r) * 128 + k0 + c];
            __nv_bfloat16 h0, h1, h2, h3, l0, l1, l2, l3;
            split_bf16(v.x, h0, l0); split_bf16(v.y, h1, l1);
            split_bf16(v.z, h2, l2); split_bf16(v.w, h3, l3);
            __nv_bfloat162 ph0 = {h0, h1}, ph1 = {h2, h3};
            __nv_bfloat162 pl0 = {l0, l1}, pl1 = {l2, l3};
            *(uint2*)&sAh[r][c] = make_uint2(*(uint32_t*)&ph0, *(uint32_t*)&ph1);
            *(uint2*)&sAl[r][c] = make_uint2(*(uint32_t*)&pl0, *(uint32_t*)&pl1);
        }
#pragma unroll
        for (int it = 0; it < 2; it++) {
            int i = tid + it * 256;
            int r = i >> 2, q = i & 3;
            *(uint4*)&sBh[r][q * 8] = *(const uint4*)&Bh_g[r * 128 + k0 + q * 8];
            *(uint4*)&sBl[r][q * 8] = *(const uint4*)&Bl_g[r * 128 + k0 + q * 8];
        }
        __syncthreads();
#pragma unroll
        for (int pass = 0; pass < 3; pass++) {
            const uint32_t aBase = (pass < 2) ? sAh_b : sAl_b;
            const uint32_t bBase = (pass == 1) ? sBl_b : sBh_b;
#pragma unroll
            for (int ks = 0; ks < 2; ks++) {
                uint32_t af[2][4];
#pragma unroll
                for (int mt = 0; mt < 2; mt++) {
                    uint32_t addr = aBase + ((a_row + mt * 16) * SKP + ks * 16 + a_khalf) * 2;
                    asm volatile("ldmatrix.sync.aligned.m8n8.x4.shared.b16 {%0,%1,%2,%3}, [%4];"
                        : "=r"(af[mt][0]), "=r"(af[mt][1]), "=r"(af[mt][2]), "=r"(af[mt][3])
                        : "r"(addr));
                }
#pragma unroll
                for (int nt = 0; nt < NT; nt++) {
                    uint32_t b0, b1;
                    uint32_t addr = bBase + ((b_row + nt * 8) * SKP + ks * 16 + b_khalf) * 2;
                    asm volatile("ldmatrix.sync.aligned.m8n8.x2.shared.b16 {%0,%1}, [%2];"
                        : "=r"(b0), "=r"(b1) : "r"(addr));
#pragma unroll
                    for (int mt = 0; mt < 2; mt++) {
                        asm volatile(
                            "mma.sync.aligned.m16n8k16.row.col.f32.bf16.bf16.f32 "
                            "{%0,%1,%2,%3}, {%4,%5,%6,%7}, {%8,%9}, {%0,%1,%2,%3};"
                            : "+f"(acc[mt][nt][0]), "+f"(acc[mt][nt][1]),
                              "+f"(acc[mt][nt][2]), "+f"(acc[mt][nt][3])
                            : "r"(af[mt][0]), "r"(af[mt][1]), "r"(af[mt][2]), "r"(af[mt][3]),
                              "r"(b0), "r"(b1));
                    }
                }
            }
        }
        __syncthreads();
    }
#pragma unroll
    for (int mt = 0; mt < 2; mt++) {
        int r0 = m0 + warp_m + mt * 16 + (lane >> 2);
        int r1 = r0 + 8;
#pragma unroll
        for (int nt = 0; nt < NT; nt++) {
            int n0 = warp_n + nt * 8 + 2 * (lane & 3);
            if (r0 < N_NODES)
                __stcs((float2*)&Ch[(size_t)r0 * 128 + n0],
                       make_float2(acc[mt][nt][0], acc[mt][nt][1]));
            if (r1 < N_NODES)
                __stcs((float2*)&Ch[(size_t)r1 * 128 + n0],
                       make_float2(acc[mt][nt][2], acc[mt][nt][3]));
        }
    }
}

// ---------------- FUSED: agg128 (CSR gather + bias + relu + bf16 split) -> gemm2 ----------------
// A tile full K=128 resident in smem (stride 136); B = W3 full K resident.
#define SKPA 136
#define SM_AH 0
#define SM_AL 34816
#define SM_BH 69632
#define SM_BL 87040
#define SMEM_FUSED 104448

__global__ void __launch_bounds__(256) agg_gemm2_both(const float* __restrict__ b1,
                                                      const float* __restrict__ b2) {
    extern __shared__ char smem[];
    __nv_bfloat16* sAh = (__nv_bfloat16*)(smem + SM_AH);
    __nv_bfloat16* sAl = (__nv_bfloat16*)(smem + SM_AL);
    __nv_bfloat16* sBh = (__nv_bfloat16*)(smem + SM_BH);
    __nv_bfloat16* sBl = (__nv_bfloat16*)(smem + SM_BL);

    const int tid = threadIdx.x;
    const int wid = tid >> 5, lane = tid & 31;
    const int m0 = blockIdx.x * 128;

    // ---- stage 1: aggregate 16 nodes per warp into the A tile ----
#pragma unroll 1
    for (int t = 0; t < 16; t++) {
        int r = wid * 16 + t;
        int node = m0 + r;
        float4 acc = make_float4(0.f, 0.f, 0.f, 0.f);
        if (node < N2) {
            float inv = g_invdeg[node];
            acc = *(const float4*)&g_h[(size_t)node * 128 + lane * 4];
            acc.x *= inv; acc.y *= inv; acc.z *= inv; acc.w *= inv;
            int i = g_rowstart[node], end = g_rowstart[node + 1];
            for (; i + 3 < end; i += 4) {
                int s0 = g_csr_src[i],     s1 = g_csr_src[i + 1];
                int s2 = g_csr_src[i + 2], s3 = g_csr_src[i + 3];
                float n0 = g_csr_norm[i],     n1 = g_csr_norm[i + 1];
                float n2 = g_csr_norm[i + 2], n3 = g_csr_norm[i + 3];
                float4 v0 = *(const float4*)&g_h[(size_t)s0 * 128 + lane * 4];
                float4 v1 = *(const float4*)&g_h[(size_t)s1 * 128 + lane * 4];
                float4 v2 = *(const float4*)&g_h[(size_t)s2 * 128 + lane * 4];
                float4 v3 = *(const float4*)&g_h[(size_t)s3 * 128 + lane * 4];
                acc.x = fmaf(v0.x, n0, fmaf(v1.x, n1, fmaf(v2.x, n2, fmaf(v3.x, n3, acc.x))));
                acc.y = fmaf(v0.y, n0, fmaf(v1.y, n1, fmaf(v2.y, n2, fmaf(v3.y, n3, acc.y))));
                acc.z = fmaf(v0.z, n0, fmaf(v1.z, n1, fmaf(v2.z, n2, fmaf(v3.z, n3, acc.z))));
                acc.w = fmaf(v0.w, n0, fmaf(v1.w, n1, fmaf(v2.w, n2, fmaf(v3.w, n3, acc.w))));
            }
            for (; i < end; i++) {
                int s0 = g_csr_src[i];
                float n0 = g_csr_norm[i];
                float4 v0 = *(const float4*)&g_h[(size_t)s0 * 128 + lane * 4];
                acc.x = fmaf(v0.x, n0, acc.x);
                acc.y = fmaf(v0.y, n0, acc.y);
                acc.z = fmaf(v0.z, n0, acc.z);
                acc.w = fmaf(v0.w, n0, acc.w);
            }
            const float* b = (node >= N_NODES) ? b2 : b1;
            float4 bb = ((const float4*)b)[lane];
            acc.x = fmaxf(acc.x + bb.x, 0.f); acc.y = fmaxf(acc.y + bb.y, 0.f);
            acc.z = fmaxf(acc.z + bb.z, 0.f); acc.w = fmaxf(acc.w + bb.w, 0.f);
        }
        __nv_bfloat16 h0, h1, h2, h3, l0, l1, l2, l3;
        split_bf16(acc.x, h0, l0); split_bf16(acc.y, h1, l1);
        split_bf16(acc.z, h2, l2); split_bf16(acc.w, h3, l3);
        __nv_bfloat162 ph0 = {h0, h1}, ph1 = {h2, h3}, pl0 = {l0, l1}, pl1 = {l2, l3};
        *(uint2*)&sAh[r * SKPA + lane * 4] = make_uint2(*(uint32_t*)&ph0, *(uint32_t*)&ph1);
        *(uint2*)&sAl[r * SKPA + lane * 4] = make_uint2(*(uint32_t*)&pl0, *(uint32_t*)&pl1);
    }
    // ---- load B (W3) full K ----
#pragma unroll
    for (int it = 0; it < 4; it++) {
        int i = tid + it * 256;          // 1024 uint4 per tile
        int r = i >> 4, q = i & 15;
        *(uint4*)&sBh[r * SKPA + q * 8] = *(const uint4*)&g_w3h[r * 128 + q * 8];
        *(uint4*)&sBl[r * SKPA + q * 8] = *(const uint4*)&g_w3l[r * 128 + q * 8];
    }
    __syncthreads();

    // ---- stage 2: gemm over full resident tiles ----
    constexpr int NT = 4;
    const int warp_m = (wid & 3) * 32;
    const int warp_n = (wid >> 2) * 32;
    float acc[2][NT][4];
#pragma unroll
    for (int mt = 0; mt < 2; mt++)
#pragma unroll
        for (int nt = 0; nt < NT; nt++)
#pragma unroll
            for (int r = 0; r < 4; r++) acc[mt][nt][r] = 0.0f;

    const uint32_t sAh_b = smem_u32(sAh);
    const uint32_t sAl_b = smem_u32(sAl);
    const uint32_t sBh_b = smem_u32(sBh);
    const uint32_t sBl_b = smem_u32(sBl);
    const int a_row = warp_m + (lane & 15);
    const int a_khalf = (lane >> 4) << 3;
    const int b_row = warp_n + (lane & 7);
    const int b_khalf = lane & 8;

#pragma unroll
    for (int pass = 0; pass < 3; pass++) {
        const uint32_t aBase = (pass < 2) ? sAh_b : sAl_b;
        const uint32_t bBase = (pass == 1) ? sBl_b : sBh_b;
#pragma unroll
        for (int ks = 0; ks < 8; ks++) {
            uint32_t af[2][4];
#pragma unroll
            for (int mt = 0; mt < 2; mt++) {
                uint32_t addr = aBase + ((a_row + mt * 16) * SKPA + ks * 16 + a_khalf) * 2;
                asm volatile("ldmatrix.sync.aligned.m8n8.x4.shared.b16 {%0,%1,%2,%3}, [%4];"
                    : "=r"(af[mt][0]), "=r"(af[mt][1]), "=r"(af[mt][2]), "=r"(af[mt][3])
                    : "r"(addr));
            }
#pragma unroll
            for (int nt = 0; nt < NT; nt++) {
                uint32_t b0, b1;
                uint32_t addr = bBase + ((b_row + nt * 8) * SKPA + ks * 16 + b_khalf) * 2;
                asm volatile("ldmatrix.sync.aligned.m8n8.x2.shared.b16 {%0,%1}, [%2];"
                    : "=r"(b0), "=r"(b1) : "r"(addr));
#pragma unroll
                for (int mt = 0; mt < 2; mt++) {
                    asm volatile(
                        "mma.sync.aligned.m16n8k16.row.col.f32.bf16.bf16.f32 "
                        "{%0,%1,%2,%3}, {%4,%5,%6,%7}, {%8,%9}, {%0,%1,%2,%3};"
                        : "+f"(acc[mt][nt][0]), "+f"(acc[mt][nt][1]),
                          "+f"(acc[mt][nt][2]), "+f"(acc[mt][nt][3])
                        : "r"(af[mt][0]), "r"(af[mt][1]), "r"(af[mt][2]), "r"(af[mt][3]),
                          "r"(b0), "r"(b1));
                }
            }
        }
    }
#pragma unroll
    for (int mt = 0; mt < 2; mt++) {
        int r0 = m0 + warp_m + mt * 16 + (lane >> 2);
        int r1 = r0 + 8;
#pragma unroll
        for (int nt = 0; nt < NT; nt++) {
            int n0 = warp_n + nt * 8 + 2 * (lane & 3);
            if (r0 < N2)
                __stcs((float2*)&g_h3[(size_t)r0 * 64 + n0],
                       make_float2(acc[mt][nt][0], acc[mt][nt][1]));
            if (r1 < N2)
                __stcs((float2*)&g_h3[(size_t)r1 * 64 + n0],
                       make_float2(acc[mt][nt][2], acc[mt][nt][3]));
        }
    }
}

// ---------------- CSR aggregation C=64, both nets; fused +b3 -> zs|zt ----------------
__global__ void __launch_bounds__(256) agg64_both(const float* __restrict__ b3,
                                                  float* __restrict__ out) {
    int node = blockIdx.x * 16 + (threadIdx.x >> 4);
    int l = threadIdx.x & 15;
    if (node >= N2) return;
    float inv = g_invdeg[node];
    float4 acc = *(const float4*)&g_h3[(size_t)node * 64 + l * 4];
    acc.x *= inv; acc.y *= inv; acc.z *= inv; acc.w *= inv;
    int i = g_rowstart[node], end = g_rowstart[node + 1];
    for (; i + 3 < end; i += 4) {
        int s0 = g_csr_src[i],     s1 = g_csr_src[i + 1];
        int s2 = g_csr_src[i + 2], s3 = g_csr_src[i + 3];
        float n0 = g_csr_norm[i],     n1 = g_csr_norm[i + 1];
        float n2 = g_csr_norm[i + 2], n3 = g_csr_norm[i + 3];
        float4 v0 = *(const float4*)&g_h3[(size_t)s0 * 64 + l * 4];
        float4 v1 = *(const float4*)&g_h3[(size_t)s1 * 64 + l * 4];
        float4 v2 = *(const float4*)&g_h3[(size_t)s2 * 64 + l * 4];
        float4 v3 = *(const float4*)&g_h3[(size_t)s3 * 64 + l * 4];
        acc.x = fmaf(v0.x, n0, fmaf(v1.x, n1, fmaf(v2.x, n2, fmaf(v3.x, n3, acc.x))));
        acc.y = fmaf(v0.y, n0, fmaf(v1.y, n1, fmaf(v2.y, n2, fmaf(v3.y, n3, acc.y))));
        acc.z = fmaf(v0.z, n0, fmaf(v1.z, n1, fmaf(v2.z, n2, fmaf(v3.z, n3, acc.z))));
        acc.w = fmaf(v0.w, n0, fmaf(v1.w, n1, fmaf(v2.w, n2, fmaf(v3.w, n3, acc.w))));
    }
    for (; i < end; i++) {
        int s0 = g_csr_src[i];
        float n0 = g_csr_norm[i];
        float4 v0 = *(const float4*)&g_h3[(size_t)s0 * 64 + l * 4];
        acc.x = fmaf(v0.x, n0, acc.x);
        acc.y = fmaf(v0.y, n0, acc.y);
        acc.z = fmaf(v0.z, n0, acc.z);
        acc.w = fmaf(v0.w, n0, acc.w);
    }
    float4 bb = ((const float4*)b3)[l];
    acc.x += bb.x; acc.y += bb.y; acc.z += bb.z; acc.w += bb.w;
    *(float4*)&out[(size_t)node * 64 + l * 4] = acc;   // zs|zt contiguous
}

// ---------------- decoder, CSR-ordered: z[dst] loaded once per node ----------------
__global__ void __launch_bounds__(256) decoder_csr(const float* __restrict__ z,
                                                   float* __restrict__ p) {
    int node = blockIdx.x * 16 + (threadIdx.x >> 4);
    int l = threadIdx.x & 15;
    if (node >= N2) return;
    float4 zd = *(const float4*)&z[(size_t)node * 64 + l * 4];
    int i = g_rowstart[node], end = g_rowstart[node + 1];
    for (; i + 1 < end; i += 2) {
        int s0 = g_csr_src[i], s1 = g_csr_src[i + 1];
        int e0 = g_csr_eidx[i], e1 = g_csr_eidx[i + 1];
        float4 a0 = *(const float4*)&z[(size_t)s0 * 64 + l * 4];
        float4 a1 = *(const float4*)&z[(size_t)s1 * 64 + l * 4];
        float v0 = a0.x * zd.x + a0.y * zd.y + a0.z * zd.z + a0.w * zd.w;
        float v1 = a1.x * zd.x + a1.y * zd.y + a1.z * zd.z + a1.w * zd.w;
        v0 += __shfl_xor_sync(0xffffffffu, v0, 8);
        v1 += __shfl_xor_sync(0xffffffffu, v1, 8);
        v0 += __shfl_xor_sync(0xffffffffu, v0, 4);
        v1 += __shfl_xor_sync(0xffffffffu, v1, 4);
        v0 += __shfl_xor_sync(0xffffffffu, v0, 2);
        v1 += __shfl_xor_sync(0xffffffffu, v1, 2);
        v0 += __shfl_xor_sync(0xffffffffu, v0, 1);
        v1 += __shfl_xor_sync(0xffffffffu, v1, 1);
        if (l == 0) {
            p[e0] = 1.0f / (1.0f + expf(-v0));
            p[e1] = 1.0f / (1.0f + expf(-v1));
        }
    }
    if (i < end) {
        int s0 = g_csr_src[i];
        int e0 = g_csr_eidx[i];
        float4 a0 = *(const float4*)&z[(size_t)s0 * 64 + l * 4];
        float v0 = a0.x * zd.x + a0.y * zd.y + a0.z * zd.z + a0.w * zd.w;
        v0 += __shfl_xor_sync(0xffffffffu, v0, 8);
        v0 += __shfl_xor_sync(0xffffffffu, v0, 4);
        v0 += __shfl_xor_sync(0xffffffffu, v0, 2);
        v0 += __shfl_xor_sync(0xffffffffu, v0, 1);
        if (l == 0) p[e0] = 1.0f / (1.0f + expf(-v0));
    }
}

// ---------------- launch ----------------
extern "C" void kernel_launch(void* const* d_in, const int* in_sizes, int n_in,
                              void* d_out, int out_size) {
    const float* xs = (const float*)d_in[0];
    const float* xt = (const float*)d_in[1];
    const int* s_ei = (const int*)d_in[2];
    const int* t_ei = (const int*)d_in[3];
    const float* W1 = (const float*)d_in[4];
    const float* b1 = (const float*)d_in[5];
    const float* W2 = (const float*)d_in[6];
    const float* b2 = (const float*)d_in[7];
    const float* W3 = (const float*)d_in[8];
    const float* b3 = (const float*)d_in[9];

    float* out = (float*)d_out;
    float* z = out;                               // zs|zt [2N,64]
    float* p = out + (size_t)N2 * 64;             // ps|pt [2E]

    int* cnt;
    cudaGetSymbolAddress((void**)&cnt, g_cnt);

    static bool attr_set = false;
    if (!attr_set) {
        cudaFuncSetAttribute(agg_gemm2_both, cudaFuncAttributeMaxDynamicSharedMemorySize,
                             SMEM_FUSED);
        attr_set = true;
    }

    const int NB_N2 = (N2 + 255) / 256;           // 782
    const int NB_E2 = (E2 + 255) / 256;           // 3907
    const int NB_G2 = (N2 + 127) / 128;           // 1563
    const int NB_A64 = (N2 + 15) / 16;            // 12500

    cudaStream_t s2 = g_side.s;

    // fork: CSR build chain on side stream, overlapped with prep+gemm1 on main
    cudaEventRecord(g_side.ev_fork, 0);
    cudaStreamWaitEvent(s2, g_side.ev_fork, 0);

    cudaMemsetAsync(cnt, 0, N2 * sizeof(int), s2);
    deg_count_both<<<NB_E2, 256, 0, s2>>>(s_ei, t_ei);
    scan1_kernel<<<NB_N2, 256, 0, s2>>>();
    scan2_kernel<<<1, 1024, 0, s2>>>(NB_N2);
    scan3_kernel<<<NB_N2, 256, 0, s2>>>();
    csr_fill_both<<<NB_E2, 256, 0, s2>>>(s_ei, t_ei);
    cudaEventRecord(g_side.ev_join, s2);

    prep_weights_kernel<<<64, 256>>>(W1, W2, W3);
    gemm1_both<<<2 * NB1, 256>>>(xs, xt);

    // join: fused agg+gemm2 needs both CSR and gemm1 output
    cudaStreamWaitEvent(0, g_side.ev_join, 0);

    agg_gemm2_both<<<NB_G2, 256, SMEM_FUSED>>>(b1, b2);
    agg64_both<<<NB_A64, 256>>>(b3, z);
    decoder_csr<<<NB_A64, 256>>>(z, p);
}

// round 13
// speedup vs baseline: 1.3890x; 1.3890x over previous
#include <cuda_runtime.h>
#include <cuda_bf16.h>
#include <math.h>
#include <stdint.h>

#define N_NODES 100000
#define N_EDGES 500000
#define N2 (2 * N_NODES)      // 200000
#define E2 (2 * N_EDGES)      // 1000000
#define NB1 782               // gemm1 blocks per net (ceil(100000/128))

// ---------------- scratch (static device globals; no allocation) ----------------
__device__ float g_h[(size_t)N2 * 128];        // layer1 conv output, both nets
__device__ float g_h3[(size_t)N2 * 64];        // layer2 conv output, both nets
__device__ float g_dis[N2];
__device__ float g_invdeg[N2];
__device__ int g_cnt[N2];
__device__ int g_rowstart[N2 + 1];
__device__ int g_cursor[N2];
__device__ int g_blocksums[1024];
__device__ int2 g_csr_sn[E2];                  // (src global row, norm bits)
__device__ int2 g_csr_se[E2];                  // (src global row, original edge pos)
__device__ __nv_bfloat16 g_abh[(size_t)N2 * 128];
__device__ __nv_bfloat16 g_abl[(size_t)N2 * 128];
__device__ __nv_bfloat16 g_w1h[128 * 128], g_w1l[128 * 128];
__device__ __nv_bfloat16 g_w2h[128 * 128], g_w2l[128 * 128];
__device__ __nv_bfloat16 g_w3h[64 * 128],  g_w3l[64 * 128];

// ---------------- pre-created side stream + events (static init; NOT during capture) ----
struct SideStream {
    cudaStream_t s;
    cudaEvent_t ev_fork, ev_join;
    SideStream() {
        cudaStreamCreateWithFlags(&s, cudaStreamNonBlocking);
        cudaEventCreateWithFlags(&ev_fork, cudaEventDisableTiming);
        cudaEventCreateWithFlags(&ev_join, cudaEventDisableTiming);
    }
};
static SideStream g_side;

__device__ __forceinline__ uint32_t smem_u32(const void* p) {
    uint32_t a;
    asm("{ .reg .u64 t; cvta.to.shared.u64 t, %1; cvt.u32.u64 %0, t; }" : "=r"(a) : "l"(p));
    return a;
}
__device__ __forceinline__ void split_bf16(float v, __nv_bfloat16& hi, __nv_bfloat16& lo) {
    hi = __float2bfloat16_rn(v);
    lo = __float2bfloat16_rn(v - __bfloat162float(hi));
}

// ---------------- degree + CSR build (both nets concatenated) ----------------
__global__ void deg_count_both(const int* __restrict__ s_ei, const int* __restrict__ t_ei) {
    int g = blockIdx.x * blockDim.x + threadIdx.x;
    if (g >= E2) return;
    int net = (g >= N_EDGES);
    int e = g - net * N_EDGES;
    const int* ei = net ? t_ei : s_ei;
    int d = ei[N_EDGES + e];
    atomicAdd(&g_cnt[net * N_NODES + d], 1);
}

__global__ void scan1_kernel() {
    __shared__ int s[2][256];
    int tid = threadIdx.x;
    int i = blockIdx.x * 256 + tid;
    int v = (i < N2) ? g_cnt[i] : 0;
    if (i < N2) {
        float d = (float)v + 1.0f;
        g_dis[i] = rsqrtf(d);
        g_invdeg[i] = 1.0f / d;
    }
    int buf = 0;
    s[0][tid] = v;
    __syncthreads();
#pragma unroll
    for (int off = 1; off < 256; off <<= 1) {
        int nb = buf ^ 1;
        s[nb][tid] = s[buf][tid] + (tid >= off ? s[buf][tid - off] : 0);
        buf = nb;
        __syncthreads();
    }
    if (i < N2) g_rowstart[i] = s[buf][tid] - v;
    if (tid == 255) g_blocksums[blockIdx.x] = s[buf][255];
}
__global__ void scan2_kernel(int nblocks) {
    __shared__ int s[2][1024];
    int tid = threadIdx.x;
    int v = (tid < nblocks) ? g_blocksums[tid] : 0;
    int buf = 0;
    s[0][tid] = v;
    __syncthreads();
#pragma unroll
    for (int off = 1; off < 1024; off <<= 1) {
        int nb = buf ^ 1;
        s[nb][tid] = s[buf][tid] + (tid >= off ? s[buf][tid - off] : 0);
        buf = nb;
        __syncthreads();
    }
    g_blocksums[tid] = s[buf][tid] - v;
}
__global__ void scan3_kernel() {
    int i = blockIdx.x * blockDim.x + threadIdx.x;
    if (i < N2) {
        int rs = g_rowstart[i] + g_blocksums[i >> 8];
        g_rowstart[i] = rs;
        g_cursor[i] = rs;
    }
    if (i == 0) g_rowstart[N2] = E2;
}
__global__ void csr_fill_both(const int* __restrict__ s_ei, const int* __restrict__ t_ei) {
    int g = blockIdx.x * blockDim.x + threadIdx.x;
    if (g >= E2) return;
    int net = (g >= N_EDGES);
    int e = g - net * N_EDGES;
    const int* ei = net ? t_ei : s_ei;
    int s = net * N_NODES + ei[e];
    int d = net * N_NODES + ei[N_EDGES + e];
    int pos = atomicAdd(&g_cursor[d], 1);
    float nrm = g_dis[s] * g_dis[d];
    g_csr_sn[pos] = make_int2(s, __float_as_int(nrm));
    g_csr_se[pos] = make_int2(s, g);
}

// ---------------- weight prep ----------------
__global__ void prep_weights_kernel(const float* __restrict__ W1, const float* __restrict__ W2,
                                    const float* __restrict__ W3) {
    int tid = blockIdx.x * blockDim.x + threadIdx.x;
    if (tid < 128 * 128) {
        int n = tid >> 7, k = tid & 127;
        __nv_bfloat16 hi, lo;
        split_bf16(W1[k * 128 + n], hi, lo);
        g_w1h[n * 128 + k] = hi; g_w1l[n * 128 + k] = lo;
        split_bf16(W2[k * 128 + n], hi, lo);
        g_w2h[n * 128 + k] = hi; g_w2l[n * 128 + k] = lo;
        if (n < 64) {
            split_bf16(W3[k * 64 + n], hi, lo);
            g_w3h[n * 128 + k] = hi; g_w3l[n * 128 + k] = lo;
        }
    }
}

// ---------------- gemm1: bf16-split HMMA, both nets, chunked K ----------------
#define SKP 40

__global__ void __launch_bounds__(256) gemm1_both(
        const float* __restrict__ xs, const float* __restrict__ xt) {
    constexpr int NT = 8;
    __shared__ __nv_bfloat16 sAh[128][SKP];
    __shared__ __nv_bfloat16 sAl[128][SKP];
    __shared__ __nv_bfloat16 sBh[128][SKP];
    __shared__ __nv_bfloat16 sBl[128][SKP];

    const int tid = threadIdx.x;
    const int wid = tid >> 5, lane = tid & 31;
    const int warp_m = (wid & 3) * 32;
    const int warp_n = (wid >> 2) * 64;
    const int net = (blockIdx.x >= NB1);
    const int m0 = (blockIdx.x - net * NB1) * 128;
    const float* Af = net ? xt : xs;
    const __nv_bfloat16* Bh_g = net ? g_w2h : g_w1h;
    const __nv_bfloat16* Bl_g = net ? g_w2l : g_w1l;
    float* Ch = g_h + (size_t)net * N_NODES * 128;

    float acc[2][NT][4];
#pragma unroll
    for (int mt = 0; mt < 2; mt++)
#pragma unroll
        for (int nt = 0; nt < NT; nt++)
#pragma unroll
            for (int r = 0; r < 4; r++) acc[mt][nt][r] = 0.0f;

    const uint32_t sAh_b = smem_u32(&sAh[0][0]);
    const uint32_t sAl_b = smem_u32(&sAl[0][0]);
    const uint32_t sBh_b = smem_u32(&sBh[0][0]);
    const uint32_t sBl_b = smem_u32(&sBl[0][0]);
    const int a_row = warp_m + (lane & 15);
    const int a_khalf = (lane >> 4) << 3;
    const int b_row = warp_n + (lane & 7);
    const int b_khalf = lane & 8;

    for (int k0 = 0; k0 < 128; k0 += 32) {
#pragma unroll
        for (int it = 0; it < 4; it++) {
            int i = tid + it * 256;
            int r = i >> 3, c = (i & 7) * 4;
            float4 v = make_float4(0.f, 0.f, 0.f, 0.f);
            if (m0 + r < N_NODES) v = *(const float4*)&Af[(size_t)(m0 + r) * 128 + k0 + c];
            __nv_bfloat16 h0, h1, h2, h3, l0, l1, l2, l3;
            split_bf16(v.x, h0, l0); split_bf16(v.y, h1, l1);
            split_bf16(v.z, h2, l2); split_bf16(v.w, h3, l3);
            __nv_bfloat162 ph0 = {h0, h1}, ph1 = {h2, h3};
            __nv_bfloat162 pl0 = {l0, l1}, pl1 = {l2, l3};
            *(uint2*)&sAh[r][c] = make_uint2(*(uint32_t*)&ph0, *(uint32_t*)&ph1);
            *(uint2*)&sAl[r][c] = make_uint2(*(uint32_t*)&pl0, *(uint32_t*)&pl1);
        }
#pragma unroll
        for (int it = 0; it < 2; it++) {
            int i = tid + it * 256;
            int r = i >> 2, q = i & 3;
            *(uint4*)&sBh[r][q * 8] = *(const uint4*)&Bh_g[r * 128 + k0 + q * 8];
            *(uint4*)&sBl[r][q * 8] = *(const uint4*)&Bl_g[r * 128 + k0 + q * 8];
        }
        __syncthreads();
#pragma unroll
        for (int pass = 0; pass < 3; pass++) {
            const uint32_t aBase = (pass < 2) ? sAh_b : sAl_b;
            const uint32_t bBase = (pass == 1) ? sBl_b : sBh_b;
#pragma unroll
            for (int ks = 0; ks < 2; ks++) {
                uint32_t af[2][4];
#pragma unroll
                for (int mt = 0; mt < 2; mt++) {
                    uint32_t addr = aBase + ((a_row + mt * 16) * SKP + ks * 16 + a_khalf) * 2;
                    asm volatile("ldmatrix.sync.aligned.m8n8.x4.shared.b16 {%0,%1,%2,%3}, [%4];"
                        : "=r"(af[mt][0]), "=r"(af[mt][1]), "=r"(af[mt][2]), "=r"(af[mt][3])
                        : "r"(addr));
                }
#pragma unroll
                for (int nt = 0; nt < NT; nt++) {
                    uint32_t b0, b1;
                    uint32_t addr = bBase + ((b_row + nt * 8) * SKP + ks * 16 + b_khalf) * 2;
                    asm volatile("ldmatrix.sync.aligned.m8n8.x2.shared.b16 {%0,%1}, [%2];"
                        : "=r"(b0), "=r"(b1) : "r"(addr));
#pragma unroll
                    for (int mt = 0; mt < 2; mt++) {
                        asm volatile(
                            "mma.sync.aligned.m16n8k16.row.col.f32.bf16.bf16.f32 "
                            "{%0,%1,%2,%3}, {%4,%5,%6,%7}, {%8,%9}, {%0,%1,%2,%3};"
                            : "+f"(acc[mt][nt][0]), "+f"(acc[mt][nt][1]),
                              "+f"(acc[mt][nt][2]), "+f"(acc[mt][nt][3])
                            : "r"(af[mt][0]), "r"(af[mt][1]), "r"(af[mt][2]), "r"(af[mt][3]),
                              "r"(b0), "r"(b1));
                    }
                }
            }
        }
        __syncthreads();
    }
#pragma unroll
    for (int mt = 0; mt < 2; mt++) {
        int r0 = m0 + warp_m + mt * 16 + (lane >> 2);
        int r1 = r0 + 8;
#pragma unroll
        for (int nt = 0; nt < NT; nt++) {
            int n0 = warp_n + nt * 8 + 2 * (lane & 3);
            if (r0 < N_NODES)
                __stcs((float2*)&Ch[(size_t)r0 * 128 + n0],
                       make_float2(acc[mt][nt][0], acc[mt][nt][1]));
            if (r1 < N_NODES)
                __stcs((float2*)&Ch[(size_t)r1 * 128 + n0],
                       make_float2(acc[mt][nt][2], acc[mt][nt][3]));
        }
    }
}

// layer2: single GEMM over M=200000 (shared W3), A pre-split bf16
__global__ void __launch_bounds__(256) gemm2_both() {
    constexpr int NT = 4;
    __shared__ __nv_bfloat16 sAh[128][SKP];
    __shared__ __nv_bfloat16 sAl[128][SKP];
    __shared__ __nv_bfloat16 sBh[64][SKP];
    __shared__ __nv_bfloat16 sBl[64][SKP];

    const int tid = threadIdx.x;
    const int wid = tid >> 5, lane = tid & 31;
    const int warp_m = (wid & 3) * 32;
    const int warp_n = (wid >> 2) * 32;
    const int m0 = blockIdx.x * 128;

    float acc[2][NT][4];
#pragma unroll
    for (int mt = 0; mt < 2; mt++)
#pragma unroll
        for (int nt = 0; nt < NT; nt++)
#pragma unroll
            for (int r = 0; r < 4; r++) acc[mt][nt][r] = 0.0f;

    const uint32_t sAh_b = smem_u32(&sAh[0][0]);
    const uint32_t sAl_b = smem_u32(&sAl[0][0]);
    const uint32_t sBh_b = smem_u32(&sBh[0][0]);
    const uint32_t sBl_b = smem_u32(&sBl[0][0]);
    const int a_row = warp_m + (lane & 15);
    const int a_khalf = (lane >> 4) << 3;
    const int b_row = warp_n + (lane & 7);
    const int b_khalf = lane & 8;

    for (int k0 = 0; k0 < 128; k0 += 32) {
#pragma unroll
        for (int it = 0; it < 2; it++) {
            int i = tid + it * 256;
            int r = i >> 2, q = i & 3;
            uint4 vh = make_uint4(0, 0, 0, 0), vl = make_uint4(0, 0, 0, 0);
            if (m0 + r < N2) {
                vh = *(const uint4*)&g_abh[(size_t)(m0 + r) * 128 + k0 + q * 8];
                vl = *(const uint4*)&g_abl[(size_t)(m0 + r) * 128 + k0 + q * 8];
            }
            *(uint4*)&sAh[r][q * 8] = vh;
            *(uint4*)&sAl[r][q * 8] = vl;
        }
        {
            int i = tid;
            int r = i >> 2, q = i & 3;
            *(uint4*)&sBh[r][q * 8] = *(const uint4*)&g_w3h[r * 128 + k0 + q * 8];
            *(uint4*)&sBl[r][q * 8] = *(const uint4*)&g_w3l[r * 128 + k0 + q * 8];
        }
        __syncthreads();
#pragma unroll
        for (int pass = 0; pass < 3; pass++) {
            const uint32_t aBase = (pass < 2) ? sAh_b : sAl_b;
            const uint32_t bBase = (pass == 1) ? sBl_b : sBh_b;
#pragma unroll
            for (int ks = 0; ks < 2; ks++) {
                uint32_t af[2][4];
#pragma unroll
                for (int mt = 0; mt < 2; mt++) {
                    uint32_t addr = aBase + ((a_row + mt * 16) * SKP + ks * 16 + a_khalf) * 2;
                    asm volatile("ldmatrix.sync.aligned.m8n8.x4.shared.b16 {%0,%1,%2,%3}, [%4];"
                        : "=r"(af[mt][0]), "=r"(af[mt][1]), "=r"(af[mt][2]), "=r"(af[mt][3])
                        : "r"(addr));
                }
#pragma unroll
                for (int nt = 0; nt < NT; nt++) {
                    uint32_t b0, b1;
                    uint32_t addr = bBase + ((b_row + nt * 8) * SKP + ks * 16 + b_khalf) * 2;
                    asm volatile("ldmatrix.sync.aligned.m8n8.x2.shared.b16 {%0,%1}, [%2];"
                        : "=r"(b0), "=r"(b1) : "r"(addr));
#pragma unroll
                    for (int mt = 0; mt < 2; mt++) {
                        asm volatile(
                            "mma.sync.aligned.m16n8k16.row.col.f32.bf16.bf16.f32 "
                            "{%0,%1,%2,%3}, {%4,%5,%6,%7}, {%8,%9}, {%0,%1,%2,%3};"
                            : "+f"(acc[mt][nt][0]), "+f"(acc[mt][nt][1]),
                              "+f"(acc[mt][nt][2]), "+f"(acc[mt][nt][3])
                            : "r"(af[mt][0]), "r"(af[mt][1]), "r"(af[mt][2]), "r"(af[mt][3]),
                              "r"(b0), "r"(b1));
                    }
                }
            }
        }
        __syncthreads();
    }
#pragma unroll
    for (int mt = 0; mt < 2; mt++) {
        int r0 = m0 + warp_m + mt * 16 + (lane >> 2);
        int r1 = r0 + 8;
#pragma unroll
        for (int nt = 0; nt < NT; nt++) {
            int n0 = warp_n + nt * 8 + 2 * (lane & 3);
            if (r0 < N2)
                __stcs((float2*)&g_h3[(size_t)r0 * 64 + n0],
                       make_float2(acc[mt][nt][0], acc[mt][nt][1]));
            if (r1 < N2)
                __stcs((float2*)&g_h3[(size_t)r1 * 64 + n0],
                       make_float2(acc[mt][nt][2], acc[mt][nt][3]));
        }
    }
}

// ---------------- CSR aggregation C=128, both nets; fused bias+relu+bf16 split ----------------
__global__ void __launch_bounds__(256) agg128_both(const float* __restrict__ b1,
                                                   const float* __restrict__ b2) {
    int node = blockIdx.x * 8 + (threadIdx.x >> 5);     // global row [0, 2N)
    int lane = threadIdx.x & 31;
    if (node >= N2) return;
    float inv = g_invdeg[node];
    float4 acc = *(const float4*)&g_h[(size_t)node * 128 + lane * 4];
    acc.x *= inv; acc.y *= inv; acc.z *= inv; acc.w *= inv;
    int i = g_rowstart[node], end = g_rowstart[node + 1];
    // 6-edge unrolled gather for MLP; packed (src,norm) records
    for (; i + 5 < end; i += 6) {
        int2 r0 = g_csr_sn[i],     r1 = g_csr_sn[i + 1], r2 = g_csr_sn[i + 2];
        int2 r3 = g_csr_sn[i + 3], r4 = g_csr_sn[i + 4], r5 = g_csr_sn[i + 5];
        float4 v0 = *(const float4*)&g_h[(size_t)r0.x * 128 + lane * 4];
        float4 v1 = *(const float4*)&g_h[(size_t)r1.x * 128 + lane * 4];
        float4 v2 = *(const float4*)&g_h[(size_t)r2.x * 128 + lane * 4];
        float4 v3 = *(const float4*)&g_h[(size_t)r3.x * 128 + lane * 4];
        float4 v4 = *(const float4*)&g_h[(size_t)r4.x * 128 + lane * 4];
        float4 v5 = *(const float4*)&g_h[(size_t)r5.x * 128 + lane * 4];
        float n0 = __int_as_float(r0.y), n1 = __int_as_float(r1.y), n2 = __int_as_float(r2.y);
        float n3 = __int_as_float(r3.y), n4 = __int_as_float(r4.y), n5 = __int_as_float(r5.y);
        acc.x = fmaf(v0.x, n0, fmaf(v1.x, n1, fmaf(v2.x, n2,
                fmaf(v3.x, n3, fmaf(v4.x, n4, fmaf(v5.x, n5, acc.x))))));
        acc.y = fmaf(v0.y, n0, fmaf(v1.y, n1, fmaf(v2.y, n2,
                fmaf(v3.y, n3, fmaf(v4.y, n4, fmaf(v5.y, n5, acc.y))))));
        acc.z = fmaf(v0.z, n0, fmaf(v1.z, n1, fmaf(v2.z, n2,
                fmaf(v3.z, n3, fmaf(v4.z, n4, fmaf(v5.z, n5, acc.z))))));
        acc.w = fmaf(v0.w, n0, fmaf(v1.w, n1, fmaf(v2.w, n2,
                fmaf(v3.w, n3, fmaf(v4.w, n4, fmaf(v5.w, n5, acc.w))))));
    }
    for (; i < end; i++) {
        int2 r0 = g_csr_sn[i];
        float n0 = __int_as_float(r0.y);
        float4 v0 = *(const float4*)&g_h[(size_t)r0.x * 128 + lane * 4];
        acc.x = fmaf(v0.x, n0, acc.x);
        acc.y = fmaf(v0.y, n0, acc.y);
        acc.z = fmaf(v0.z, n0, acc.z);
        acc.w = fmaf(v0.w, n0, acc.w);
    }
    const float* b = (node >= N_NODES) ? b2 : b1;
    float4 bb = ((const float4*)b)[lane];
    acc.x = fmaxf(acc.x + bb.x, 0.f); acc.y = fmaxf(acc.y + bb.y, 0.f);
    acc.z = fmaxf(acc.z + bb.z, 0.f); acc.w = fmaxf(acc.w + bb.w, 0.f);
    __nv_bfloat16 h0, h1, h2, h3, l0, l1, l2, l3;
    split_bf16(acc.x, h0, l0); split_bf16(acc.y, h1, l1);
    split_bf16(acc.z, h2, l2); split_bf16(acc.w, h3, l3);
    __nv_bfloat162 ph0 = {h0, h1}, ph1 = {h2, h3}, pl0 = {l0, l1}, pl1 = {l2, l3};
    size_t idx = (size_t)node * 32 + lane;
    __stcs((uint2*)&((uint2*)g_abh)[idx], make_uint2(*(uint32_t*)&ph0, *(uint32_t*)&ph1));
    __stcs((uint2*)&((uint2*)g_abl)[idx], make_uint2(*(uint32_t*)&pl0, *(uint32_t*)&pl1));
}

// ---------------- CSR aggregation C=64, both nets; fused +b3 -> zs|zt ----------------
__global__ void __launch_bounds__(256) agg64_both(const float* __restrict__ b3,
                                                  float* __restrict__ out) {
    int node = blockIdx.x * 16 + (threadIdx.x >> 4);
    int l = threadIdx.x & 15;
    if (node >= N2) return;
    float inv = g_invdeg[node];
    float4 acc = *(const float4*)&g_h3[(size_t)node * 64 + l * 4];
    acc.x *= inv; acc.y *= inv; acc.z *= inv; acc.w *= inv;
    int i = g_rowstart[node], end = g_rowstart[node + 1];
    for (; i + 3 < end; i += 4) {
        int2 r0 = g_csr_sn[i],     r1 = g_csr_sn[i + 1];
        int2 r2 = g_csr_sn[i + 2], r3 = g_csr_sn[i + 3];
        float4 v0 = *(const float4*)&g_h3[(size_t)r0.x * 64 + l * 4];
        float4 v1 = *(const float4*)&g_h3[(size_t)r1.x * 64 + l * 4];
        float4 v2 = *(const float4*)&g_h3[(size_t)r2.x * 64 + l * 4];
        float4 v3 = *(const float4*)&g_h3[(size_t)r3.x * 64 + l * 4];
        float n0 = __int_as_float(r0.y), n1 = __int_as_float(r1.y);
        float n2 = __int_as_float(r2.y), n3 = __int_as_float(r3.y);
        acc.x = fmaf(v0.x, n0, fmaf(v1.x, n1, fmaf(v2.x, n2, fmaf(v3.x, n3, acc.x))));
        acc.y = fmaf(v0.y, n0, fmaf(v1.y, n1, fmaf(v2.y, n2, fmaf(v3.y, n3, acc.y))));
        acc.z = fmaf(v0.z, n0, fmaf(v1.z, n1, fmaf(v2.z, n2, fmaf(v3.z, n3, acc.z))));
        acc.w = fmaf(v0.w, n0, fmaf(v1.w, n1, fmaf(v2.w, n2, fmaf(v3.w, n3, acc.w))));
    }
    for (; i < end; i++) {
        int2 r0 = g_csr_sn[i];
        float n0 = __int_as_float(r0.y);
        float4 v0 = *(const float4*)&g_h3[(size_t)r0.x * 64 + l * 4];
        acc.x = fmaf(v0.x, n0, acc.x);
        acc.y = fmaf(v0.y, n0, acc.y);
        acc.z = fmaf(v0.z, n0, acc.z);
        acc.w = fmaf(v0.w, n0, acc.w);
    }
    float4 bb = ((const float4*)b3)[l];
    acc.x += bb.x; acc.y += bb.y; acc.z += bb.z; acc.w += bb.w;
    *(float4*)&out[(size_t)node * 64 + l * 4] = acc;   // zs|zt contiguous
}

// ---------------- decoder, CSR-ordered: z[dst] loaded once per node ----------------
__global__ void __launch_bounds__(256) decoder_csr(const float* __restrict__ z,
                                                   float* __restrict__ p) {
    int node = blockIdx.x * 16 + (threadIdx.x >> 4);
    int l = threadIdx.x & 15;
    if (node >= N2) return;
    float4 zd = *(const float4*)&z[(size_t)node * 64 + l * 4];
    int i = g_rowstart[node], end = g_rowstart[node + 1];
    for (; i + 1 < end; i += 2) {
        int2 r0 = g_csr_se[i], r1 = g_csr_se[i + 1];
        float4 a0 = *(const float4*)&z[(size_t)r0.x * 64 + l * 4];
        float4 a1 = *(const float4*)&z[(size_t)r1.x * 64 + l * 4];
        float v0 = a0.x * zd.x + a0.y * zd.y + a0.z * zd.z + a0.w * zd.w;
        float v1 = a1.x * zd.x + a1.y * zd.y + a1.z * zd.z + a1.w * zd.w;
        v0 += __shfl_xor_sync(0xffffffffu, v0, 8);
        v1 += __shfl_xor_sync(0xffffffffu, v1, 8);
        v0 += __shfl_xor_sync(0xffffffffu, v0, 4);
        v1 += __shfl_xor_sync(0xffffffffu, v1, 4);
        v0 += __shfl_xor_sync(0xffffffffu, v0, 2);
        v1 += __shfl_xor_sync(0xffffffffu, v1, 2);
        v0 += __shfl_xor_sync(0xffffffffu, v0, 1);
        v1 += __shfl_xor_sync(0xffffffffu, v1, 1);
        if (l == 0) {
            p[r0.y] = 1.0f / (1.0f + expf(-v0));
            p[r1.y] = 1.0f / (1.0f + expf(-v1));
        }
    }
    if (i < end) {
        int2 r0 = g_csr_se[i];
        float4 a0 = *(const float4*)&z[(size_t)r0.x * 64 + l * 4];
        float v0 = a0.x * zd.x + a0.y * zd.y + a0.z * zd.z + a0.w * zd.w;
        v0 += __shfl_xor_sync(0xffffffffu, v0, 8);
        v0 += __shfl_xor_sync(0xffffffffu, v0, 4);
        v0 += __shfl_xor_sync(0xffffffffu, v0, 2);
        v0 += __shfl_xor_sync(0xffffffffu, v0, 1);
        if (l == 0) p[r0.y] = 1.0f / (1.0f + expf(-v0));
    }
}

// ---------------- launch ----------------
extern "C" void kernel_launch(void* const* d_in, const int* in_sizes, int n_in,
                              void* d_out, int out_size) {
    const float* xs = (const float*)d_in[0];
    const float* xt = (const float*)d_in[1];
    const int* s_ei = (const int*)d_in[2];
    const int* t_ei = (const int*)d_in[3];
    const float* W1 = (const float*)d_in[4];
    const float* b1 = (const float*)d_in[5];
    const float* W2 = (const float*)d_in[6];
    const float* b2 = (const float*)d_in[7];
    const float* W3 = (const float*)d_in[8];
    const float* b3 = (const float*)d_in[9];

    float* out = (float*)d_out;
    float* z = out;                               // zs|zt [2N,64]
    float* p = out + (size_t)N2 * 64;             // ps|pt [2E]

    int* cnt;
    cudaGetSymbolAddress((void**)&cnt, g_cnt);

    const int NB_N2 = (N2 + 255) / 256;           // 782
    const int NB_E2 = (E2 + 255) / 256;           // 3907
    const int NB_G2 = (N2 + 127) / 128;           // 1563
    const int NB_A128 = (N2 + 7) / 8;             // 25000
    const int NB_A64 = (N2 + 15) / 16;            // 12500

    cudaStream_t s2 = g_side.s;

    // fork: CSR build chain on side stream, overlapped with prep+gemm1 on main
    cudaEventRecord(g_side.ev_fork, 0);
    cudaStreamWaitEvent(s2, g_side.ev_fork, 0);

    cudaMemsetAsync(cnt, 0, N2 * sizeof(int), s2);
    deg_count_both<<<NB_E2, 256, 0, s2>>>(s_ei, t_ei);
    scan1_kernel<<<NB_N2, 256, 0, s2>>>();
    scan2_kernel<<<1, 1024, 0, s2>>>(NB_N2);
    scan3_kernel<<<NB_N2, 256, 0, s2>>>();
    csr_fill_both<<<NB_E2, 256, 0, s2>>>(s_ei, t_ei);
    cudaEventRecord(g_side.ev_join, s2);

    prep_weights_kernel<<<64, 256>>>(W1, W2, W3);
    gemm1_both<<<2 * NB1, 256>>>(xs, xt);

    // join: agg128 needs both CSR and gemm1 output
    cudaStreamWaitEvent(0, g_side.ev_join, 0);

    agg128_both<<<NB_A128, 256>>>(b1, b2);
    gemm2_both<<<NB_G2, 256>>>();
    agg64_both<<<NB_A64, 256>>>(b3, z);
    decoder_csr<<<NB_A64, 256>>>(z, p);
}

// round 14
// speedup vs baseline: 1.4398x; 1.0366x over previous
#include <cuda_runtime.h>
#include <cuda_bf16.h>
#include <math.h>
#include <stdint.h>

#define N_NODES 100000
#define N_EDGES 500000
#define N2 (2 * N_NODES)      // 200000
#define E2 (2 * N_EDGES)      // 1000000
#define NB1 782               // gemm1 blocks per net (ceil(100000/128))

// ---------------- scratch (static device globals; no allocation) ----------------
__device__ float g_h[(size_t)N2 * 128];        // layer1 conv output, both nets
__device__ float g_h3[(size_t)N2 * 64];        // layer2 conv output, both nets
__device__ float g_dis[N2];
__device__ float g_invdeg[N2];
__device__ int g_cnt[N2];
__device__ int g_rowstart[N2 + 1];
__device__ int g_cursor[N2];
__device__ int g_blocksums[1024];
__device__ int g_csr_src[E2];                  // global rows (net*N + s)
__device__ int g_csr_eidx[E2];                 // original edge position (net*E + e)
__device__ float g_csr_norm[E2];
__device__ __nv_bfloat16 g_abh[(size_t)N2 * 128];
__device__ __nv_bfloat16 g_abl[(size_t)N2 * 128];
__device__ __nv_bfloat16 g_w1h[128 * 128], g_w1l[128 * 128];
__device__ __nv_bfloat16 g_w2h[128 * 128], g_w2l[128 * 128];
__device__ __nv_bfloat16 g_w3h[64 * 128],  g_w3l[64 * 128];

// ---------------- pre-created side stream + events (static init; NOT during capture) ----
struct SideStream {
    cudaStream_t s;
    cudaEvent_t ev_fork, ev_join;
    SideStream() {
        cudaStreamCreateWithFlags(&s, cudaStreamNonBlocking);
        cudaEventCreateWithFlags(&ev_fork, cudaEventDisableTiming);
        cudaEventCreateWithFlags(&ev_join, cudaEventDisableTiming);
    }
};
static SideStream g_side;

__device__ __forceinline__ uint32_t smem_u32(const void* p) {
    uint32_t a;
    asm("{ .reg .u64 t; cvta.to.shared.u64 t, %1; cvt.u32.u64 %0, t; }" : "=r"(a) : "l"(p));
    return a;
}
__device__ __forceinline__ void split_bf16(float v, __nv_bfloat16& hi, __nv_bfloat16& lo) {
    hi = __float2bfloat16_rn(v);
    lo = __float2bfloat16_rn(v - __bfloat162float(hi));
}

// ---------------- degree + CSR build (both nets concatenated) ----------------
__global__ void deg_count_both(const int* __restrict__ s_ei, const int* __restrict__ t_ei) {
    int g = blockIdx.x * blockDim.x + threadIdx.x;
    if (g >= E2) return;
    int net = (g >= N_EDGES);
    int e = g - net * N_EDGES;
    const int* ei = net ? t_ei : s_ei;
    int d = ei[N_EDGES + e];
    atomicAdd(&g_cnt[net * N_NODES + d], 1);
}

// block scan + deg finish fused
__global__ void scan1_kernel() {
    __shared__ int s[2][256];
    int tid = threadIdx.x;
    int i = blockIdx.x * 256 + tid;
    int v = (i < N2) ? g_cnt[i] : 0;
    if (i < N2) {
        float d = (float)v + 1.0f;
        g_dis[i] = rsqrtf(d);
        g_invdeg[i] = 1.0f / d;
    }
    int buf = 0;
    s[0][tid] = v;
    __syncthreads();
#pragma unroll
    for (int off = 1; off < 256; off <<= 1) {
        int nb = buf ^ 1;
        s[nb][tid] = s[buf][tid] + (tid >= off ? s[buf][tid - off] : 0);
        buf = nb;
        __syncthreads();
    }
    if (i < N2) g_rowstart[i] = s[buf][tid] - v;
    if (tid == 255) g_blocksums[blockIdx.x] = s[buf][255];
}
__global__ void scan2_kernel(int nblocks) {
    __shared__ int s[2][1024];
    int tid = threadIdx.x;
    int v = (tid < nblocks) ? g_blocksums[tid] : 0;
    int buf = 0;
    s[0][tid] = v;
    __syncthreads();
#pragma unroll
    for (int off = 1; off < 1024; off <<= 1) {
        int nb = buf ^ 1;
        s[nb][tid] = s[buf][tid] + (tid >= off ? s[buf][tid - off] : 0);
        buf = nb;
        __syncthreads();
    }
    g_blocksums[tid] = s[buf][tid] - v;
}
__global__ void scan3_kernel() {
    int i = blockIdx.x * blockDim.x + threadIdx.x;
    if (i < N2) {
        int rs = g_rowstart[i] + g_blocksums[i >> 8];
        g_rowstart[i] = rs;
        g_cursor[i] = rs;
    }
    if (i == 0) g_rowstart[N2] = E2;
}
__global__ void csr_fill_both(const int* __restrict__ s_ei, const int* __restrict__ t_ei) {
    int g = blockIdx.x * blockDim.x + threadIdx.x;
    if (g >= E2) return;
    int net = (g >= N_EDGES);
    int e = g - net * N_EDGES;
    const int* ei = net ? t_ei : s_ei;
    int s = net * N_NODES + ei[e];
    int d = net * N_NODES + ei[N_EDGES + e];
    int pos = atomicAdd(&g_cursor[d], 1);
    g_csr_src[pos] = s;
    g_csr_eidx[pos] = g;
    g_csr_norm[pos] = g_dis[s] * g_dis[d];
}

// ---------------- weight prep ----------------
__global__ void prep_weights_kernel(const float* __restrict__ W1, const float* __restrict__ W2,
                                    const float* __restrict__ W3) {
    int tid = blockIdx.x * blockDim.x + threadIdx.x;
    if (tid < 128 * 128) {
        int n = tid >> 7, k = tid & 127;
        __nv_bfloat16 hi, lo;
        split_bf16(W1[k * 128 + n], hi, lo);
        g_w1h[n * 128 + k] = hi; g_w1l[n * 128 + k] = lo;
        split_bf16(W2[k * 128 + n], hi, lo);
        g_w2h[n * 128 + k] = hi; g_w2l[n * 128 + k] = lo;
        if (n < 64) {
            split_bf16(W3[k * 64 + n], hi, lo);
            g_w3h[n * 128 + k] = hi; g_w3l[n * 128 + k] = lo;
        }
    }
}

// ---------------- gemm1: bf16-split HMMA, both nets, chunked K ----------------
#define SKP 40

__global__ void __launch_bounds__(256) gemm1_both(
        const float* __restrict__ xs, const float* __restrict__ xt) {
    constexpr int NT = 8;
    __shared__ __nv_bfloat16 sAh[128][SKP];
    __shared__ __nv_bfloat16 sAl[128][SKP];
    __shared__ __nv_bfloat16 sBh[128][SKP];
    __shared__ __nv_bfloat16 sBl[128][SKP];

    const int tid = threadIdx.x;
    const int wid = tid >> 5, lane = tid & 31;
    const int warp_m = (wid & 3) * 32;
    const int warp_n = (wid >> 2) * 64;
    const int net = (blockIdx.x >= NB1);
    const int m0 = (blockIdx.x - net * NB1) * 128;
    const float* Af = net ? xt : xs;
    const __nv_bfloat16* Bh_g = net ? g_w2h : g_w1h;
    const __nv_bfloat16* Bl_g = net ? g_w2l : g_w1l;
    float* Ch = g_h + (size_t)net * N_NODES * 128;

    float acc[2][NT][4];
#pragma unroll
    for (int mt = 0; mt < 2; mt++)
#pragma unroll
        for (int nt = 0; nt < NT; nt++)
#pragma unroll
            for (int r = 0; r < 4; r++) acc[mt][nt][r] = 0.0f;

    const uint32_t sAh_b = smem_u32(&sAh[0][0]);
    const uint32_t sAl_b = smem_u32(&sAl[0][0]);
    const uint32_t sBh_b = smem_u32(&sBh[0][0]);
    const uint32_t sBl_b = smem_u32(&sBl[0][0]);
    const int a_row = warp_m + (lane & 15);
    const int a_khalf = (lane >> 4) << 3;
    const int b_row = warp_n + (lane & 7);
    const int b_khalf = lane & 8;

    for (int k0 = 0; k0 < 128; k0 += 32) {
#pragma unroll
        for (int it = 0; it < 4; it++) {
            int i = tid + it * 256;
            int r = i >> 3, c = (i & 7) * 4;
            float4 v = make_float4(0.f, 0.f, 0.f, 0.f);
            if (m0 + r < N_NODES) v = *(const float4*)&Af[(size_t)(m0 + r) * 128 + k0 + c];
            __nv_bfloat16 h0, h1, h2, h3, l0, l1, l2, l3;
            split_bf16(v.x, h0, l0); split_bf16(v.y, h1, l1);
            split_bf16(v.z, h2, l2); split_bf16(v.w, h3, l3);
            __nv_bfloat162 ph0 = {h0, h1}, ph1 = {h2, h3};
            __nv_bfloat162 pl0 = {l0, l1}, pl1 = {l2, l3};
            *(uint2*)&sAh[r][c] = make_uint2(*(uint32_t*)&ph0, *(uint32_t*)&ph1);
            *(uint2*)&sAl[r][c] = make_uint2(*(uint32_t*)&pl0, *(uint32_t*)&pl1);
        }
#pragma unroll
        for (int it = 0; it < 2; it++) {
            int i = tid + it * 256;
            int r = i >> 2, q = i & 3;
            *(uint4*)&sBh[r][q * 8] = *(const uint4*)&Bh_g[r * 128 + k0 + q * 8];
            *(uint4*)&sBl[r][q * 8] = *(const uint4*)&Bl_g[r * 128 + k0 + q * 8];
        }
        __syncthreads();
#pragma unroll
        for (int pass = 0; pass < 3; pass++) {
            const uint32_t aBase = (pass < 2) ? sAh_b : sAl_b;
            const uint32_t bBase = (pass == 1) ? sBl_b : sBh_b;
#pragma unroll
            for (int ks = 0; ks < 2; ks++) {
                uint32_t af[2][4];
#pragma unroll
                for (int mt = 0; mt < 2; mt++) {
                    uint32_t addr = aBase + ((a_row + mt * 16) * SKP + ks * 16 + a_khalf) * 2;
                    asm volatile("ldmatrix.sync.aligned.m8n8.x4.shared.b16 {%0,%1,%2,%3}, [%4];"
                        : "=r"(af[mt][0]), "=r"(af[mt][1]), "=r"(af[mt][2]), "=r"(af[mt][3])
                        : "r"(addr));
                }
#pragma unroll
                for (int nt = 0; nt < NT; nt++) {
                    uint32_t b0, b1;
                    uint32_t addr = bBase + ((b_row + nt * 8) * SKP + ks * 16 + b_khalf) * 2;
                    asm volatile("ldmatrix.sync.aligned.m8n8.x2.shared.b16 {%0,%1}, [%2];"
                        : "=r"(b0), "=r"(b1) : "r"(addr));
#pragma unroll
                    for (int mt = 0; mt < 2; mt++) {
                        asm volatile(
                            "mma.sync.aligned.m16n8k16.row.col.f32.bf16.bf16.f32 "
                            "{%0,%1,%2,%3}, {%4,%5,%6,%7}, {%8,%9}, {%0,%1,%2,%3};"
                            : "+f"(acc[mt][nt][0]), "+f"(acc[mt][nt][1]),
                              "+f"(acc[mt][nt][2]), "+f"(acc[mt][nt][3])
                            : "r"(af[mt][0]), "r"(af[mt][1]), "r"(af[mt][2]), "r"(af[mt][3]),
                              "r"(b0), "r"(b1));
                    }
                }
            }
        }
        __syncthreads();
    }
#pragma unroll
    for (int mt = 0; mt < 2; mt++) {
        int r0 = m0 + warp_m + mt * 16 + (lane >> 2);
        int r1 = r0 + 8;
#pragma unroll
        for (int nt = 0; nt < NT; nt++) {
            int n0 = warp_n + nt * 8 + 2 * (lane & 3);
            if (r0 < N_NODES)
                __stcs((float2*)&Ch[(size_t)r0 * 128 + n0],
                       make_float2(acc[mt][nt][0], acc[mt][nt][1]));
            if (r1 < N_NODES)
                __stcs((float2*)&Ch[(size_t)r1 * 128 + n0],
                       make_float2(acc[mt][nt][2], acc[mt][nt][3]));
        }
    }
}

// layer2: single GEMM over M=200000 (shared W3), A pre-split bf16
__global__ void __launch_bounds__(256) gemm2_both() {
    constexpr int NT = 4;
    __shared__ __nv_bfloat16 sAh[128][SKP];
    __shared__ __nv_bfloat16 sAl[128][SKP];
    __shared__ __nv_bfloat16 sBh[64][SKP];
    __shared__ __nv_bfloat16 sBl[64][SKP];

    const int tid = threadIdx.x;
    const int wid = tid >> 5, lane = tid & 31;
    const int warp_m = (wid & 3) * 32;
    const int warp_n = (wid >> 2) * 32;
    const int m0 = blockIdx.x * 128;

    float acc[2][NT][4];
#pragma unroll
    for (int mt = 0; mt < 2; mt++)
#pragma unroll
        for (int nt = 0; nt < NT; nt++)
#pragma unroll
            for (int r = 0; r < 4; r++) acc[mt][nt][r] = 0.0f;

    const uint32_t sAh_b = smem_u32(&sAh[0][0]);
    const uint32_t sAl_b = smem_u32(&sAl[0][0]);
    const uint32_t sBh_b = smem_u32(&sBh[0][0]);
    const uint32_t sBl_b = smem_u32(&sBl[0][0]);
    const int a_row = warp_m + (lane & 15);
    const int a_khalf = (lane >> 4) << 3;
    const int b_row = warp_n + (lane & 7);
    const int b_khalf = lane & 8;

    for (int k0 = 0; k0 < 128; k0 += 32) {
#pragma unroll
        for (int it = 0; it < 2; it++) {
            int i = tid + it * 256;
            int r = i >> 2, q = i & 3;
            uint4 vh = make_uint4(0, 0, 0, 0), vl = make_uint4(0, 0, 0, 0);
            if (m0 + r < N2) {
                vh = *(const uint4*)&g_abh[(size_t)(m0 + r) * 128 + k0 + q * 8];
                vl = *(const uint4*)&g_abl[(size_t)(m0 + r) * 128 + k0 + q * 8];
            }
            *(uint4*)&sAh[r][q * 8] = vh;
            *(uint4*)&sAl[r][q * 8] = vl;
        }
        {
            int i = tid;
            int r = i >> 2, q = i & 3;
            *(uint4*)&sBh[r][q * 8] = *(const uint4*)&g_w3h[r * 128 + k0 + q * 8];
            *(uint4*)&sBl[r][q * 8] = *(const uint4*)&g_w3l[r * 128 + k0 + q * 8];
        }
        __syncthreads();
#pragma unroll
        for (int pass = 0; pass < 3; pass++) {
            const uint32_t aBase = (pass < 2) ? sAh_b : sAl_b;
            const uint32_t bBase = (pass == 1) ? sBl_b : sBh_b;
#pragma unroll
            for (int ks = 0; ks < 2; ks++) {
                uint32_t af[2][4];
#pragma unroll
                for (int mt = 0; mt < 2; mt++) {
                    uint32_t addr = aBase + ((a_row + mt * 16) * SKP + ks * 16 + a_khalf) * 2;
                    asm volatile("ldmatrix.sync.aligned.m8n8.x4.shared.b16 {%0,%1,%2,%3}, [%4];"
                        : "=r"(af[mt][0]), "=r"(af[mt][1]), "=r"(af[mt][2]), "=r"(af[mt][3])
                        : "r"(addr));
                }
#pragma unroll
                for (int nt = 0; nt < NT; nt++) {
                    uint32_t b0, b1;
                    uint32_t addr = bBase + ((b_row + nt * 8) * SKP + ks * 16 + b_khalf) * 2;
                    asm volatile("ldmatrix.sync.aligned.m8n8.x2.shared.b16 {%0,%1}, [%2];"
                        : "=r"(b0), "=r"(b1) : "r"(addr));
#pragma unroll
                    for (int mt = 0; mt < 2; mt++) {
                        asm volatile(
                            "mma.sync.aligned.m16n8k16.row.col.f32.bf16.bf16.f32 "
                            "{%0,%1,%2,%3}, {%4,%5,%6,%7}, {%8,%9}, {%0,%1,%2,%3};"
                            : "+f"(acc[mt][nt][0]), "+f"(acc[mt][nt][1]),
                              "+f"(acc[mt][nt][2]), "+f"(acc[mt][nt][3])
                            : "r"(af[mt][0]), "r"(af[mt][1]), "r"(af[mt][2]), "r"(af[mt][3]),
                              "r"(b0), "r"(b1));
                    }
                }
            }
        }
        __syncthreads();
    }
#pragma unroll
    for (int mt = 0; mt < 2; mt++) {
        int r0 = m0 + warp_m + mt * 16 + (lane >> 2);
        int r1 = r0 + 8;
#pragma unroll
        for (int nt = 0; nt < NT; nt++) {
            int n0 = warp_n + nt * 8 + 2 * (lane & 3);
            if (r0 < N2)
                __stcs((float2*)&g_h3[(size_t)r0 * 64 + n0],
                       make_float2(acc[mt][nt][0], acc[mt][nt][1]));
            if (r1 < N2)
                __stcs((float2*)&g_h3[(size_t)r1 * 64 + n0],
                       make_float2(acc[mt][nt][2], acc[mt][nt][3]));
        }
    }
}

// ---------------- CSR aggregation C=128, both nets; fused bias+relu+bf16 split ----------------
__global__ void __launch_bounds__(256) agg128_both(const float* __restrict__ b1,
                                                   const float* __restrict__ b2) {
    int node = blockIdx.x * 8 + (threadIdx.x >> 5);     // global row [0, 2N)
    int lane = threadIdx.x & 31;
    if (node >= N2) return;
    float inv = g_invdeg[node];
    float4 acc = *(const float4*)&g_h[(size_t)node * 128 + lane * 4];
    acc.x *= inv; acc.y *= inv; acc.z *= inv; acc.w *= inv;
    int i = g_rowstart[node], end = g_rowstart[node + 1];
    // 4-edge unrolled gather for MLP
    for (; i + 3 < end; i += 4) {
        int s0 = g_csr_src[i],     s1 = g_csr_src[i + 1];
        int s2 = g_csr_src[i + 2], s3 = g_csr_src[i + 3];
        float n0 = g_csr_norm[i],     n1 = g_csr_norm[i + 1];
        float n2 = g_csr_norm[i + 2], n3 = g_csr_norm[i + 3];
        float4 v0 = *(const float4*)&g_h[(size_t)s0 * 128 + lane * 4];
        float4 v1 = *(const float4*)&g_h[(size_t)s1 * 128 + lane * 4];
        float4 v2 = *(const float4*)&g_h[(size_t)s2 * 128 + lane * 4];
        float4 v3 = *(const float4*)&g_h[(size_t)s3 * 128 + lane * 4];
        acc.x = fmaf(v0.x, n0, fmaf(v1.x, n1, fmaf(v2.x, n2, fmaf(v3.x, n3, acc.x))));
        acc.y = fmaf(v0.y, n0, fmaf(v1.y, n1, fmaf(v2.y, n2, fmaf(v3.y, n3, acc.y))));
        acc.z = fmaf(v0.z, n0, fmaf(v1.z, n1, fmaf(v2.z, n2, fmaf(v3.z, n3, acc.z))));
        acc.w = fmaf(v0.w, n0, fmaf(v1.w, n1, fmaf(v2.w, n2, fmaf(v3.w, n3, acc.w))));
    }
    for (; i < end; i++) {
        int s0 = g_csr_src[i];
        float n0 = g_csr_norm[i];
        float4 v0 = *(const float4*)&g_h[(size_t)s0 * 128 + lane * 4];
        acc.x = fmaf(v0.x, n0, acc.x);
        acc.y = fmaf(v0.y, n0, acc.y);
        acc.z = fmaf(v0.z, n0, acc.z);
        acc.w = fmaf(v0.w, n0, acc.w);
    }
    const float* b = (node >= N_NODES) ? b2 : b1;
    float4 bb = ((const float4*)b)[lane];
    acc.x = fmaxf(acc.x + bb.x, 0.f); acc.y = fmaxf(acc.y + bb.y, 0.f);
    acc.z = fmaxf(acc.z + bb.z, 0.f); acc.w = fmaxf(acc.w + bb.w, 0.f);
    __nv_bfloat16 h0, h1, h2, h3, l0, l1, l2, l3;
    split_bf16(acc.x, h0, l0); split_bf16(acc.y, h1, l1);
    split_bf16(acc.z, h2, l2); split_bf16(acc.w, h3, l3);
    __nv_bfloat162 ph0 = {h0, h1}, ph1 = {h2, h3}, pl0 = {l0, l1}, pl1 = {l2, l3};
    size_t idx = (size_t)node * 32 + lane;
    // streaming stores: keep h resident in L2 for the gathers
    __stcs((uint2*)&((uint2*)g_abh)[idx], make_uint2(*(uint32_t*)&ph0, *(uint32_t*)&ph1));
    __stcs((uint2*)&((uint2*)g_abl)[idx], make_uint2(*(uint32_t*)&pl0, *(uint32_t*)&pl1));
}

// ---------------- CSR aggregation C=64, both nets; fused +b3 -> zs|zt ----------------
__global__ void __launch_bounds__(256) agg64_both(const float* __restrict__ b3,
                                                  float* __restrict__ out) {
    int node = blockIdx.x * 16 + (threadIdx.x >> 4);
    int l = threadIdx.x & 15;
    if (node >= N2) return;
    float inv = g_invdeg[node];
    float4 acc = *(const float4*)&g_h3[(size_t)node * 64 + l * 4];
    acc.x *= inv; acc.y *= inv; acc.z *= inv; acc.w *= inv;
    int i = g_rowstart[node], end = g_rowstart[node + 1];
    for (; i + 3 < end; i += 4) {
        int s0 = g_csr_src[i],     s1 = g_csr_src[i + 1];
        int s2 = g_csr_src[i + 2], s3 = g_csr_src[i + 3];
        float n0 = g_csr_norm[i],     n1 = g_csr_norm[i + 1];
        float n2 = g_csr_norm[i + 2], n3 = g_csr_norm[i + 3];
        float4 v0 = *(const float4*)&g_h3[(size_t)s0 * 64 + l * 4];
        float4 v1 = *(const float4*)&g_h3[(size_t)s1 * 64 + l * 4];
        float4 v2 = *(const float4*)&g_h3[(size_t)s2 * 64 + l * 4];
        float4 v3 = *(const float4*)&g_h3[(size_t)s3 * 64 + l * 4];
        acc.x = fmaf(v0.x, n0, fmaf(v1.x, n1, fmaf(v2.x, n2, fmaf(v3.x, n3, acc.x))));
        acc.y = fmaf(v0.y, n0, fmaf(v1.y, n1, fmaf(v2.y, n2, fmaf(v3.y, n3, acc.y))));
        acc.z = fmaf(v0.z, n0, fmaf(v1.z, n1, fmaf(v2.z, n2, fmaf(v3.z, n3, acc.z))));
        acc.w = fmaf(v0.w, n0, fmaf(v1.w, n1, fmaf(v2.w, n2, fmaf(v3.w, n3, acc.w))));
    }
    for (; i < end; i++) {
        int s0 = g_csr_src[i];
        float n0 = g_csr_norm[i];
        float4 v0 = *(const float4*)&g_h3[(size_t)s0 * 64 + l * 4];
        acc.x = fmaf(v0.x, n0, acc.x);
        acc.y = fmaf(v0.y, n0, acc.y);
        acc.z = fmaf(v0.z, n0, acc.z);
        acc.w = fmaf(v0.w, n0, acc.w);
    }
    float4 bb = ((const float4*)b3)[l];
    acc.x += bb.x; acc.y += bb.y; acc.z += bb.z; acc.w += bb.w;
    *(float4*)&out[(size_t)node * 64 + l * 4] = acc;   // zs|zt contiguous
}

// ---------------- decoder, CSR-ordered: z[dst] loaded once per node ----------------
__global__ void __launch_bounds__(256) decoder_csr(const float* __restrict__ z,
                                                   float* __restrict__ p) {
    int node = blockIdx.x * 16 + (threadIdx.x >> 4);
    int l = threadIdx.x & 15;
    if (node >= N2) return;
    float4 zd = *(const float4*)&z[(size_t)node * 64 + l * 4];
    int i = g_rowstart[node], end = g_rowstart[node + 1];
    for (; i + 1 < end; i += 2) {
        int s0 = g_csr_src[i], s1 = g_csr_src[i + 1];
        int e0 = g_csr_eidx[i], e1 = g_csr_eidx[i + 1];
        float4 a0 = *(const float4*)&z[(size_t)s0 * 64 + l * 4];
        float4 a1 = *(const float4*)&z[(size_t)s1 * 64 + l * 4];
        float v0 = a0.x * zd.x + a0.y * zd.y + a0.z * zd.z + a0.w * zd.w;
        float v1 = a1.x * zd.x + a1.y * zd.y + a1.z * zd.z + a1.w * zd.w;
        v0 += __shfl_xor_sync(0xffffffffu, v0, 8);
        v1 += __shfl_xor_sync(0xffffffffu, v1, 8);
        v0 += __shfl_xor_sync(0xffffffffu, v0, 4);
        v1 += __shfl_xor_sync(0xffffffffu, v1, 4);
        v0 += __shfl_xor_sync(0xffffffffu, v0, 2);
        v1 += __shfl_xor_sync(0xffffffffu, v1, 2);
        v0 += __shfl_xor_sync(0xffffffffu, v0, 1);
        v1 += __shfl_xor_sync(0xffffffffu, v1, 1);
        if (l == 0) {
            p[e0] = 1.0f / (1.0f + expf(-v0));
            p[e1] = 1.0f / (1.0f + expf(-v1));
        }
    }
    if (i < end) {
        int s0 = g_csr_src[i];
        int e0 = g_csr_eidx[i];
        float4 a0 = *(const float4*)&z[(size_t)s0 * 64 + l * 4];
        float v0 = a0.x * zd.x + a0.y * zd.y + a0.z * zd.z + a0.w * zd.w;
        v0 += __shfl_xor_sync(0xffffffffu, v0, 8);
        v0 += __shfl_xor_sync(0xffffffffu, v0, 4);
        v0 += __shfl_xor_sync(0xffffffffu, v0, 2);
        v0 += __shfl_xor_sync(0xffffffffu, v0, 1);
        if (l == 0) p[e0] = 1.0f / (1.0f + expf(-v0));
    }
}

// ---------------- launch ----------------
extern "C" void kernel_launch(void* const* d_in, const int* in_sizes, int n_in,
                              void* d_out, int out_size) {
    const float* xs = (const float*)d_in[0];
    const float* xt = (const float*)d_in[1];
    const int* s_ei = (const int*)d_in[2];
    const int* t_ei = (const int*)d_in[3];
    const float* W1 = (const float*)d_in[4];
    const float* b1 = (const float*)d_in[5];
    const float* W2 = (const float*)d_in[6];
    const float* b2 = (const float*)d_in[7];
    const float* W3 = (const float*)d_in[8];
    const float* b3 = (const float*)d_in[9];

    float* out = (float*)d_out;
    float* z = out;                               // zs|zt [2N,64]
    float* p = out + (size_t)N2 * 64;             // ps|pt [2E]

    int* cnt;
    cudaGetSymbolAddress((void**)&cnt, g_cnt);

    const int NB_N2 = (N2 + 255) / 256;           // 782
    const int NB_E2 = (E2 + 255) / 256;           // 3907
    const int NB_G2 = (N2 + 127) / 128;           // 1563
    const int NB_A128 = (N2 + 7) / 8;             // 25000
    const int NB_A64 = (N2 + 15) / 16;            // 12500

    cudaStream_t s2 = g_side.s;

    // fork: CSR build chain on side stream, overlapped with prep+gemm1 on main
    cudaEventRecord(g_side.ev_fork, 0);
    cudaStreamWaitEvent(s2, g_side.ev_fork, 0);

    cudaMemsetAsync(cnt, 0, N2 * sizeof(int), s2);
    deg_count_both<<<NB_E2, 256, 0, s2>>>(s_ei, t_ei);
    scan1_kernel<<<NB_N2, 256, 0, s2>>>();
    scan2_kernel<<<1, 1024, 0, s2>>>(NB_N2);
    scan3_kernel<<<NB_N2, 256, 0, s2>>>();
    csr_fill_both<<<NB_E2, 256, 0, s2>>>(s_ei, t_ei);
    cudaEventRecord(g_side.ev_join, s2);

    prep_weights_kernel<<<64, 256>>>(W1, W2, W3);
    gemm1_both<<<2 * NB1, 256>>>(xs, xt);

    // join: agg128 needs both CSR and gemm1 output
    cudaStreamWaitEvent(0, g_side.ev_join, 0);

    agg128_both<<<NB_A128, 256>>>(b1, b2);
    gemm2_both<<<NB_G2, 256>>>();
    agg64_both<<<NB_A64, 256>>>(b3, z);
    decoder_csr<<<NB_A64, 256>>>(z, p);
}

// round 15
// speedup vs baseline: 1.4849x; 1.0313x over previous
#include <cuda_runtime.h>
#include <cuda_bf16.h>
#include <math.h>
#include <stdint.h>

#define N_NODES 100000
#define N_EDGES 500000
#define N2 (2 * N_NODES)      // 200000
#define E2 (2 * N_EDGES)      // 1000000
#define NB1 782               // gemm blocks per net (ceil(100000/128))

// ---------------- scratch (static device globals; no allocation) ----------------
__device__ float g_h[(size_t)N2 * 128];        // layer1 conv output, both nets
__device__ float g_h3[(size_t)N2 * 64];        // layer2 conv output, both nets
__device__ float g_dis[N2];
__device__ float g_invdeg[N2];
__device__ int g_cnt[N2];
__device__ int g_rowstart[N2 + 1];
__device__ int g_cursor[N2];
__device__ int g_blocksums[1024];
__device__ int g_csr_src[E2];                  // global rows (net*N + s)
__device__ int g_csr_eidx[E2];                 // original edge position (net*E + e)
__device__ float g_csr_norm[E2];
__device__ __nv_bfloat16 g_abh[(size_t)N2 * 128];
__device__ __nv_bfloat16 g_abl[(size_t)N2 * 128];
__device__ __nv_bfloat16 g_w1h[128 * 128], g_w1l[128 * 128];
__device__ __nv_bfloat16 g_w2h[128 * 128], g_w2l[128 * 128];
__device__ __nv_bfloat16 g_w3h[64 * 128],  g_w3l[64 * 128];

// ---------------- pre-created side stream + events (static init; NOT during capture) ----
struct SideStream {
    cudaStream_t s;
    cudaEvent_t ev_fork, ev_csr, ev_g1, ev_done;
    SideStream() {
        cudaStreamCreateWithFlags(&s, cudaStreamNonBlocking);
        cudaEventCreateWithFlags(&ev_fork, cudaEventDisableTiming);
        cudaEventCreateWithFlags(&ev_csr, cudaEventDisableTiming);
        cudaEventCreateWithFlags(&ev_g1, cudaEventDisableTiming);
        cudaEventCreateWithFlags(&ev_done, cudaEventDisableTiming);
    }
};
static SideStream g_side;

__device__ __forceinline__ uint32_t smem_u32(const void* p) {
    uint32_t a;
    asm("{ .reg .u64 t; cvta.to.shared.u64 t, %1; cvt.u32.u64 %0, t; }" : "=r"(a) : "l"(p));
    return a;
}
__device__ __forceinline__ void split_bf16(float v, __nv_bfloat16& hi, __nv_bfloat16& lo) {
    hi = __float2bfloat16_rn(v);
    lo = __float2bfloat16_rn(v - __bfloat162float(hi));
}

// ---------------- degree + CSR build (both nets concatenated) ----------------
__global__ void deg_count_both(const int* __restrict__ s_ei, const int* __restrict__ t_ei) {
    int g = blockIdx.x * blockDim.x + threadIdx.x;
    if (g >= E2) return;
    int net = (g >= N_EDGES);
    int e = g - net * N_EDGES;
    const int* ei = net ? t_ei : s_ei;
    int d = ei[N_EDGES + e];
    atomicAdd(&g_cnt[net * N_NODES + d], 1);
}

// block scan + deg finish fused
__global__ void scan1_kernel() {
    __shared__ int s[2][256];
    int tid = threadIdx.x;
    int i = blockIdx.x * 256 + tid;
    int v = (i < N2) ? g_cnt[i] : 0;
    if (i < N2) {
        float d = (float)v + 1.0f;
        g_dis[i] = rsqrtf(d);
        g_invdeg[i] = 1.0f / d;
    }
    int buf = 0;
    s[0][tid] = v;
    __syncthreads();
#pragma unroll
    for (int off = 1; off < 256; off <<= 1) {
        int nb = buf ^ 1;
        s[nb][tid] = s[buf][tid] + (tid >= off ? s[buf][tid - off] : 0);
        buf = nb;
        __syncthreads();
    }
    if (i < N2) g_rowstart[i] = s[buf][tid] - v;
    if (tid == 255) g_blocksums[blockIdx.x] = s[buf][255];
}
__global__ void scan2_kernel(int nblocks) {
    __shared__ int s[2][1024];
    int tid = threadIdx.x;
    int v = (tid < nblocks) ? g_blocksums[tid] : 0;
    int buf = 0;
    s[0][tid] = v;
    __syncthreads();
#pragma unroll
    for (int off = 1; off < 1024; off <<= 1) {
        int nb = buf ^ 1;
        s[nb][tid] = s[buf][tid] + (tid >= off ? s[buf][tid - off] : 0);
        buf = nb;
        __syncthreads();
    }
    g_blocksums[tid] = s[buf][tid] - v;
}
__global__ void scan3_kernel() {
    int i = blockIdx.x * blockDim.x + threadIdx.x;
    if (i < N2) {
        int rs = g_rowstart[i] + g_blocksums[i >> 8];
        g_rowstart[i] = rs;
        g_cursor[i] = rs;
    }
    if (i == 0) g_rowstart[N2] = E2;
}
__global__ void csr_fill_both(const int* __restrict__ s_ei, const int* __restrict__ t_ei) {
    int g = blockIdx.x * blockDim.x + threadIdx.x;
    if (g >= E2) return;
    int net = (g >= N_EDGES);
    int e = g - net * N_EDGES;
    const int* ei = net ? t_ei : s_ei;
    int s = net * N_NODES + ei[e];
    int d = net * N_NODES + ei[N_EDGES + e];
    int pos = atomicAdd(&g_cursor[d], 1);
    g_csr_src[pos] = s;
    g_csr_eidx[pos] = g;
    g_csr_norm[pos] = g_dis[s] * g_dis[d];
}

// ---------------- weight prep ----------------
__global__ void prep_weights_kernel(const float* __restrict__ W1, const float* __restrict__ W2,
                                    const float* __restrict__ W3) {
    int tid = blockIdx.x * blockDim.x + threadIdx.x;
    if (tid < 128 * 128) {
        int n = tid >> 7, k = tid & 127;
        __nv_bfloat16 hi, lo;
        split_bf16(W1[k * 128 + n], hi, lo);
        g_w1h[n * 128 + k] = hi; g_w1l[n * 128 + k] = lo;
        split_bf16(W2[k * 128 + n], hi, lo);
        g_w2h[n * 128 + k] = hi; g_w2l[n * 128 + k] = lo;
        if (n < 64) {
            split_bf16(W3[k * 64 + n], hi, lo);
            g_w3h[n * 128 + k] = hi; g_w3l[n * 128 + k] = lo;
        }
    }
}

// ---------------- gemm1: bf16-split HMMA, both nets, chunked K ----------------
#define SKP 40

__global__ void __launch_bounds__(256) gemm1_both(
        const float* __restrict__ xs, const float* __restrict__ xt) {
    constexpr int NT = 8;
    __shared__ __nv_bfloat16 sAh[128][SKP];
    __shared__ __nv_bfloat16 sAl[128][SKP];
    __shared__ __nv_bfloat16 sBh[128][SKP];
    __shared__ __nv_bfloat16 sBl[128][SKP];

    const int tid = threadIdx.x;
    const int wid = tid >> 5, lane = tid & 31;
    const int warp_m = (wid & 3) * 32;
    const int warp_n = (wid >> 2) * 64;
    const int net = (blockIdx.x >= NB1);
    const int m0 = (blockIdx.x - net * NB1) * 128;
    const float* Af = net ? xt : xs;
    const __nv_bfloat16* Bh_g = net ? g_w2h : g_w1h;
    const __nv_bfloat16* Bl_g = net ? g_w2l : g_w1l;
    float* Ch = g_h + (size_t)net * N_NODES * 128;

    float acc[2][NT][4];
#pragma unroll
    for (int mt = 0; mt < 2; mt++)
#pragma unroll
        for (int nt = 0; nt < NT; nt++)
#pragma unroll
            for (int r = 0; r < 4; r++) acc[mt][nt][r] = 0.0f;

    const uint32_t sAh_b = smem_u32(&sAh[0][0]);
    const uint32_t sAl_b = smem_u32(&sAl[0][0]);
    const uint32_t sBh_b = smem_u32(&sBh[0][0]);
    const uint32_t sBl_b = smem_u32(&sBl[0][0]);
    const int a_row = warp_m + (lane & 15);
    const int a_khalf = (lane >> 4) << 3;
    const int b_row = warp_n + (lane & 7);
    const int b_khalf = lane & 8;

    for (int k0 = 0; k0 < 128; k0 += 32) {
#pragma unroll
        for (int it = 0; it < 4; it++) {
            int i = tid + it * 256;
            int r = i >> 3, c = (i & 7) * 4;
            float4 v = make_float4(0.f, 0.f, 0.f, 0.f);
            if (m0 + r < N_NODES) v = *(const float4*)&Af[(size_t)(m0 + r) * 128 + k0 + c];
            __nv_bfloat16 h0, h1, h2, h3, l0, l1, l2, l3;
            split_bf16(v.x, h0, l0); split_bf16(v.y, h1, l1);
            split_bf16(v.z, h2, l2); split_bf16(v.w, h3, l3);
            __nv_bfloat162 ph0 = {h0, h1}, ph1 = {h2, h3};
            __nv_bfloat162 pl0 = {l0, l1}, pl1 = {l2, l3};
            *(uint2*)&sAh[r][c] = make_uint2(*(uint32_t*)&ph0, *(uint32_t*)&ph1);
            *(uint2*)&sAl[r][c] = make_uint2(*(uint32_t*)&pl0, *(uint32_t*)&pl1);
        }
#pragma unroll
        for (int it = 0; it < 2; it++) {
            int i = tid + it * 256;
            int r = i >> 2, q = i & 3;
            *(uint4*)&sBh[r][q * 8] = *(const uint4*)&Bh_g[r * 128 + k0 + q * 8];
            *(uint4*)&sBl[r][q * 8] = *(const uint4*)&Bl_g[r * 128 + k0 + q * 8];
        }
        __syncthreads();
#pragma unroll
        for (int pass = 0; pass < 3; pass++) {
            const uint32_t aBase = (pass < 2) ? sAh_b : sAl_b;
            const uint32_t bBase = (pass == 1) ? sBl_b : sBh_b;
#pragma unroll
            for (int ks = 0; ks < 2; ks++) {
                uint32_t af[2][4];
#pragma unroll
                for (int mt = 0; mt < 2; mt++) {
                    uint32_t addr = aBase + ((a_row + mt * 16) * SKP + ks * 16 + a_khalf) * 2;
                    asm volatile("ldmatrix.sync.aligned.m8n8.x4.shared.b16 {%0,%1,%2,%3}, [%4];"
                        : "=r"(af[mt][0]), "=r"(af[mt][1]), "=r"(af[mt][2]), "=r"(af[mt][3])
                        : "r"(addr));
                }
#pragma unroll
                for (int nt = 0; nt < NT; nt++) {
                    uint32_t b0, b1;
                    uint32_t addr = bBase + ((b_row + nt * 8) * SKP + ks * 16 + b_khalf) * 2;
                    asm volatile("ldmatrix.sync.aligned.m8n8.x2.shared.b16 {%0,%1}, [%2];"
                        : "=r"(b0), "=r"(b1) : "r"(addr));
#pragma unroll
                    for (int mt = 0; mt < 2; mt++) {
                        asm volatile(
                            "mma.sync.aligned.m16n8k16.row.col.f32.bf16.bf16.f32 "
                            "{%0,%1,%2,%3}, {%4,%5,%6,%7}, {%8,%9}, {%0,%1,%2,%3};"
                            : "+f"(acc[mt][nt][0]), "+f"(acc[mt][nt][1]),
                              "+f"(acc[mt][nt][2]), "+f"(acc[mt][nt][3])
                            : "r"(af[mt][0]), "r"(af[mt][1]), "r"(af[mt][2]), "r"(af[mt][3]),
                              "r"(b0), "r"(b1));
                    }
                }
            }
        }
        __syncthreads();
    }
#pragma unroll
    for (int mt = 0; mt < 2; mt++) {
        int r0 = m0 + warp_m + mt * 16 + (lane >> 2);
        int r1 = r0 + 8;
#pragma unroll
        for (int nt = 0; nt < NT; nt++) {
            int n0 = warp_n + nt * 8 + 2 * (lane & 3);
            if (r0 < N_NODES)
                __stcs((float2*)&Ch[(size_t)r0 * 128 + n0],
                       make_float2(acc[mt][nt][0], acc[mt][nt][1]));
            if (r1 < N_NODES)
                __stcs((float2*)&Ch[(size_t)r1 * 128 + n0],
                       make_float2(acc[mt][nt][2], acc[mt][nt][3]));
        }
    }
}

// ---------------- gemm2 per net: M=100000 rows starting at base ----------------
__global__ void __launch_bounds__(256) gemm2_net(int base) {
    constexpr int NT = 4;
    __shared__ __nv_bfloat16 sAh[128][SKP];
    __shared__ __nv_bfloat16 sAl[128][SKP];
    __shared__ __nv_bfloat16 sBh[64][SKP];
    __shared__ __nv_bfloat16 sBl[64][SKP];

    const int tid = threadIdx.x;
    const int wid = tid >> 5, lane = tid & 31;
    const int warp_m = (wid & 3) * 32;
    const int warp_n = (wid >> 2) * 32;
    const int m0 = base + blockIdx.x * 128;
    const int mlim = base + N_NODES;

    float acc[2][NT][4];
#pragma unroll
    for (int mt = 0; mt < 2; mt++)
#pragma unroll
        for (int nt = 0; nt < NT; nt++)
#pragma unroll
            for (int r = 0; r < 4; r++) acc[mt][nt][r] = 0.0f;

    const uint32_t sAh_b = smem_u32(&sAh[0][0]);
    const uint32_t sAl_b = smem_u32(&sAl[0][0]);
    const uint32_t sBh_b = smem_u32(&sBh[0][0]);
    const uint32_t sBl_b = smem_u32(&sBl[0][0]);
    const int a_row = warp_m + (lane & 15);
    const int a_khalf = (lane >> 4) << 3;
    const int b_row = warp_n + (lane & 7);
    const int b_khalf = lane & 8;

    for (int k0 = 0; k0 < 128; k0 += 32) {
#pragma unroll
        for (int it = 0; it < 2; it++) {
            int i = tid + it * 256;
            int r = i >> 2, q = i & 3;
            uint4 vh = make_uint4(0, 0, 0, 0), vl = make_uint4(0, 0, 0, 0);
            if (m0 + r < mlim) {
                vh = *(const uint4*)&g_abh[(size_t)(m0 + r) * 128 + k0 + q * 8];
                vl = *(const uint4*)&g_abl[(size_t)(m0 + r) * 128 + k0 + q * 8];
            }
            *(uint4*)&sAh[r][q * 8] = vh;
            *(uint4*)&sAl[r][q * 8] = vl;
        }
        {
            int i = tid;
            int r = i >> 2, q = i & 3;
            *(uint4*)&sBh[r][q * 8] = *(const uint4*)&g_w3h[r * 128 + k0 + q * 8];
            *(uint4*)&sBl[r][q * 8] = *(const uint4*)&g_w3l[r * 128 + k0 + q * 8];
        }
        __syncthreads();
#pragma unroll
        for (int pass = 0; pass < 3; pass++) {
            const uint32_t aBase = (pass < 2) ? sAh_b : sAl_b;
            const uint32_t bBase = (pass == 1) ? sBl_b : sBh_b;
#pragma unroll
            for (int ks = 0; ks < 2; ks++) {
                uint32_t af[2][4];
#pragma unroll
                for (int mt = 0; mt < 2; mt++) {
                    uint32_t addr = aBase + ((a_row + mt * 16) * SKP + ks * 16 + a_khalf) * 2;
                    asm volatile("ldmatrix.sync.aligned.m8n8.x4.shared.b16 {%0,%1,%2,%3}, [%4];"
                        : "=r"(af[mt][0]), "=r"(af[mt][1]), "=r"(af[mt][2]), "=r"(af[mt][3])
                        : "r"(addr));
                }
#pragma unroll
                for (int nt = 0; nt < NT; nt++) {
                    uint32_t b0, b1;
                    uint32_t addr = bBase + ((b_row + nt * 8) * SKP + ks * 16 + b_khalf) * 2;
                    asm volatile("ldmatrix.sync.aligned.m8n8.x2.shared.b16 {%0,%1}, [%2];"
                        : "=r"(b0), "=r"(b1) : "r"(addr));
#pragma unroll
                    for (int mt = 0; mt < 2; mt++) {
                        asm volatile(
                            "mma.sync.aligned.m16n8k16.row.col.f32.bf16.bf16.f32 "
                            "{%0,%1,%2,%3}, {%4,%5,%6,%7}, {%8,%9}, {%0,%1,%2,%3};"
                            : "+f"(acc[mt][nt][0]), "+f"(acc[mt][nt][1]),
                              "+f"(acc[mt][nt][2]), "+f"(acc[mt][nt][3])
                            : "r"(af[mt][0]), "r"(af[mt][1]), "r"(af[mt][2]), "r"(af[mt][3]),
                              "r"(b0), "r"(b1));
                    }
                }
            }
        }
        __syncthreads();
    }
#pragma unroll
    for (int mt = 0; mt < 2; mt++) {
        int r0 = m0 + warp_m + mt * 16 + (lane >> 2);
        int r1 = r0 + 8;
#pragma unroll
        for (int nt = 0; nt < NT; nt++) {
            int n0 = warp_n + nt * 8 + 2 * (lane & 3);
            if (r0 < mlim)
                __stcs((float2*)&g_h3[(size_t)r0 * 64 + n0],
                       make_float2(acc[mt][nt][0], acc[mt][nt][1]));
            if (r1 < mlim)
                __stcs((float2*)&g_h3[(size_t)r1 * 64 + n0],
                       make_float2(acc[mt][nt][2], acc[mt][nt][3]));
        }
    }
}

// ---------------- CSR aggregation C=128, per net; fused bias+relu+bf16 split ----------------
__global__ void __launch_bounds__(256) agg128_net(const float* __restrict__ b, int base) {
    int node = base + blockIdx.x * 8 + (threadIdx.x >> 5);
    int lane = threadIdx.x & 31;
    if (node >= base + N_NODES) return;
    float inv = g_invdeg[node];
    float4 acc = *(const float4*)&g_h[(size_t)node * 128 + lane * 4];
    acc.x *= inv; acc.y *= inv; acc.z *= inv; acc.w *= inv;
    int i = g_rowstart[node], end = g_rowstart[node + 1];
    // 4-edge unrolled gather for MLP
    for (; i + 3 < end; i += 4) {
        int s0 = g_csr_src[i],     s1 = g_csr_src[i + 1];
        int s2 = g_csr_src[i + 2], s3 = g_csr_src[i + 3];
        float n0 = g_csr_norm[i],     n1 = g_csr_norm[i + 1];
        float n2 = g_csr_norm[i + 2], n3 = g_csr_norm[i + 3];
        float4 v0 = *(const float4*)&g_h[(size_t)s0 * 128 + lane * 4];
        float4 v1 = *(const float4*)&g_h[(size_t)s1 * 128 + lane * 4];
        float4 v2 = *(const float4*)&g_h[(size_t)s2 * 128 + lane * 4];
        float4 v3 = *(const float4*)&g_h[(size_t)s3 * 128 + lane * 4];
        acc.x = fmaf(v0.x, n0, fmaf(v1.x, n1, fmaf(v2.x, n2, fmaf(v3.x, n3, acc.x))));
        acc.y = fmaf(v0.y, n0, fmaf(v1.y, n1, fmaf(v2.y, n2, fmaf(v3.y, n3, acc.y))));
        acc.z = fmaf(v0.z, n0, fmaf(v1.z, n1, fmaf(v2.z, n2, fmaf(v3.z, n3, acc.z))));
        acc.w = fmaf(v0.w, n0, fmaf(v1.w, n1, fmaf(v2.w, n2, fmaf(v3.w, n3, acc.w))));
    }
    for (; i < end; i++) {
        int s0 = g_csr_src[i];
        float n0 = g_csr_norm[i];
        float4 v0 = *(const float4*)&g_h[(size_t)s0 * 128 + lane * 4];
        acc.x = fmaf(v0.x, n0, acc.x);
        acc.y = fmaf(v0.y, n0, acc.y);
        acc.z = fmaf(v0.z, n0, acc.z);
        acc.w = fmaf(v0.w, n0, acc.w);
    }
    float4 bb = ((const float4*)b)[lane];
    acc.x = fmaxf(acc.x + bb.x, 0.f); acc.y = fmaxf(acc.y + bb.y, 0.f);
    acc.z = fmaxf(acc.z + bb.z, 0.f); acc.w = fmaxf(acc.w + bb.w, 0.f);
    __nv_bfloat16 h0, h1, h2, h3, l0, l1, l2, l3;
    split_bf16(acc.x, h0, l0); split_bf16(acc.y, h1, l1);
    split_bf16(acc.z, h2, l2); split_bf16(acc.w, h3, l3);
    __nv_bfloat162 ph0 = {h0, h1}, ph1 = {h2, h3}, pl0 = {l0, l1}, pl1 = {l2, l3};
    size_t idx = (size_t)node * 32 + lane;
    // streaming stores: keep h resident in L2 for the gathers
    __stcs((uint2*)&((uint2*)g_abh)[idx], make_uint2(*(uint32_t*)&ph0, *(uint32_t*)&ph1));
    __stcs((uint2*)&((uint2*)g_abl)[idx], make_uint2(*(uint32_t*)&pl0, *(uint32_t*)&pl1));
}

// ---------------- CSR aggregation C=64, per net; fused +b3 -> z ----------------
__global__ void __launch_bounds__(256) agg64_net(const float* __restrict__ b3,
                                                 float* __restrict__ out, int base) {
    int node = base + blockIdx.x * 16 + (threadIdx.x >> 4);
    int l = threadIdx.x & 15;
    if (node >= base + N_NODES) return;
    float inv = g_invdeg[node];
    float4 acc = *(const float4*)&g_h3[(size_t)node * 64 + l * 4];
    acc.x *= inv; acc.y *= inv; acc.z *= inv; acc.w *= inv;
    int i = g_rowstart[node], end = g_rowstart[node + 1];
    for (; i + 3 < end; i += 4) {
        int s0 = g_csr_src[i],     s1 = g_csr_src[i + 1];
        int s2 = g_csr_src[i + 2], s3 = g_csr_src[i + 3];
        float n0 = g_csr_norm[i],     n1 = g_csr_norm[i + 1];
        float n2 = g_csr_norm[i + 2], n3 = g_csr_norm[i + 3];
        float4 v0 = *(const float4*)&g_h3[(size_t)s0 * 64 + l * 4];
        float4 v1 = *(const float4*)&g_h3[(size_t)s1 * 64 + l * 4];
        float4 v2 = *(const float4*)&g_h3[(size_t)s2 * 64 + l * 4];
        float4 v3 = *(const float4*)&g_h3[(size_t)s3 * 64 + l * 4];
        acc.x = fmaf(v0.x, n0, fmaf(v1.x, n1, fmaf(v2.x, n2, fmaf(v3.x, n3, acc.x))));
        acc.y = fmaf(v0.y, n0, fmaf(v1.y, n1, fmaf(v2.y, n2, fmaf(v3.y, n3, acc.y))));
        acc.z = fmaf(v0.z, n0, fmaf(v1.z, n1, fmaf(v2.z, n2, fmaf(v3.z, n3, acc.z))));
        acc.w = fmaf(v0.w, n0, fmaf(v1.w, n1, fmaf(v2.w, n2, fmaf(v3.w, n3, acc.w))));
    }
    for (; i < end; i++) {
        int s0 = g_csr_src[i];
        float n0 = g_csr_norm[i];
        float4 v0 = *(const float4*)&g_h3[(size_t)s0 * 64 + l * 4];
        acc.x = fmaf(v0.x, n0, acc.x);
        acc.y = fmaf(v0.y, n0, acc.y);
        acc.z = fmaf(v0.z, n0, acc.z);
        acc.w = fmaf(v0.w, n0, acc.w);
    }
    float4 bb = ((const float4*)b3)[l];
    acc.x += bb.x; acc.y += bb.y; acc.z += bb.z; acc.w += bb.w;
    *(float4*)&out[(size_t)node * 64 + l * 4] = acc;   // zs|zt contiguous
}

// ---------------- decoder per net, CSR-ordered: z[dst] loaded once per node ----------------
__global__ void __launch_bounds__(256) decoder_net(const float* __restrict__ z,
                                                   float* __restrict__ p, int base) {
    int node = base + blockIdx.x * 16 + (threadIdx.x >> 4);
    int l = threadIdx.x & 15;
    if (node >= base + N_NODES) return;
    float4 zd = *(const float4*)&z[(size_t)node * 64 + l * 4];
    int i = g_rowstart[node], end = g_rowstart[node + 1];
    for (; i + 1 < end; i += 2) {
        int s0 = g_csr_src[i], s1 = g_csr_src[i + 1];
        int e0 = g_csr_eidx[i], e1 = g_csr_eidx[i + 1];
        float4 a0 = *(const float4*)&z[(size_t)s0 * 64 + l * 4];
        float4 a1 = *(const float4*)&z[(size_t)s1 * 64 + l * 4];
        float v0 = a0.x * zd.x + a0.y * zd.y + a0.z * zd.z + a0.w * zd.w;
        float v1 = a1.x * zd.x + a1.y * zd.y + a1.z * zd.z + a1.w * zd.w;
        v0 += __shfl_xor_sync(0xffffffffu, v0, 8);
        v1 += __shfl_xor_sync(0xffffffffu, v1, 8);
        v0 += __shfl_xor_sync(0xffffffffu, v0, 4);
        v1 += __shfl_xor_sync(0xffffffffu, v1, 4);
        v0 += __shfl_xor_sync(0xffffffffu, v0, 2);
        v1 += __shfl_xor_sync(0xffffffffu, v1, 2);
        v0 += __shfl_xor_sync(0xffffffffu, v0, 1);
        v1 += __shfl_xor_sync(0xffffffffu, v1, 1);
        if (l == 0) {
            p[e0] = 1.0f / (1.0f + expf(-v0));
            p[e1] = 1.0f / (1.0f + expf(-v1));
        }
    }
    if (i < end) {
        int s0 = g_csr_src[i];
        int e0 = g_csr_eidx[i];
        float4 a0 = *(const float4*)&z[(size_t)s0 * 64 + l * 4];
        float v0 = a0.x * zd.x + a0.y * zd.y + a0.z * zd.z + a0.w * zd.w;
        v0 += __shfl_xor_sync(0xffffffffu, v0, 8);
        v0 += __shfl_xor_sync(0xffffffffu, v0, 4);
        v0 += __shfl_xor_sync(0xffffffffu, v0, 2);
        v0 += __shfl_xor_sync(0xffffffffu, v0, 1);
        if (l == 0) p[e0] = 1.0f / (1.0f + expf(-v0));
    }
}

// ---------------- launch ----------------
extern "C" void kernel_launch(void* const* d_in, const int* in_sizes, int n_in,
                              void* d_out, int out_size) {
    const float* xs = (const float*)d_in[0];
    const float* xt = (const float*)d_in[1];
    const int* s_ei = (const int*)d_in[2];
    const int* t_ei = (const int*)d_in[3];
    const float* W1 = (const float*)d_in[4];
    const float* b1 = (const float*)d_in[5];
    const float* W2 = (const float*)d_in[6];
    const float* b2 = (const float*)d_in[7];
    const float* W3 = (const float*)d_in[8];
    const float* b3 = (const float*)d_in[9];

    float* out = (float*)d_out;
    float* z = out;                               // zs|zt [2N,64]
    float* p = out + (size_t)N2 * 64;             // ps|pt [2E]

    int* cnt;
    cudaGetSymbolAddress((void**)&cnt, g_cnt);

    const int NB_N2 = (N2 + 255) / 256;           // 782
    const int NB_E2 = (E2 + 255) / 256;           // 3907
    const int NB_A128 = (N_NODES + 7) / 8;        // 12500 per net
    const int NB_A64 = (N_NODES + 15) / 16;       // 6250 per net

    cudaStream_t s2 = g_side.s;

    // fork: CSR build chain on side stream, overlapped with prep+gemm1 on main
    cudaEventRecord(g_side.ev_fork, 0);
    cudaStreamWaitEvent(s2, g_side.ev_fork, 0);

    cudaMemsetAsync(cnt, 0, N2 * sizeof(int), s2);
    deg_count_both<<<NB_E2, 256, 0, s2>>>(s_ei, t_ei);
    scan1_kernel<<<NB_N2, 256, 0, s2>>>();
    scan2_kernel<<<1, 1024, 0, s2>>>(NB_N2);
    scan3_kernel<<<NB_N2, 256, 0, s2>>>();
    csr_fill_both<<<NB_E2, 256, 0, s2>>>(s_ei, t_ei);
    cudaEventRecord(g_side.ev_csr, s2);

    prep_weights_kernel<<<64, 256>>>(W1, W2, W3);
    gemm1_both<<<2 * NB1, 256>>>(xs, xt);
    cudaEventRecord(g_side.ev_g1, 0);

    // side stream: net-1 chain (needs gemm1 output; CSR already done on this stream)
    cudaStreamWaitEvent(s2, g_side.ev_g1, 0);
    agg128_net<<<NB_A128, 256, 0, s2>>>(b2, N_NODES);
    gemm2_net<<<NB1, 256, 0, s2>>>(N_NODES);
    agg64_net<<<NB_A64, 256, 0, s2>>>(b3, z, N_NODES);
    decoder_net<<<NB_A64, 256, 0, s2>>>(z, p, N_NODES);
    cudaEventRecord(g_side.ev_done, s2);

    // main stream: net-0 chain (needs CSR from side)
    cudaStreamWaitEvent(0, g_side.ev_csr, 0);
    agg128_net<<<NB_A128, 256>>>(b1, 0);
    gemm2_net<<<NB1, 256>>>(0);
    agg64_net<<<NB_A64, 256>>>(b3, z, 0);
    decoder_net<<<NB_A64, 256>>>(z, p, 0);

    // join: all output written before harness reads d_out
    cudaStreamWaitEvent(0, g_side.ev_done, 0);
}